// round 1
// baseline (speedup 1.0000x reference)
#include <cuda_runtime.h>
#include <cuda_bf16.h>
#include <cstdint>

#define N_NODES_MAX 50000
#define FEAT 128

// Scratch (allocation-free rule: __device__ globals)
__device__ float g_h[N_NODES_MAX * FEAT];
__device__ float g_deg[N_NODES_MAX];
__device__ float g_dinv[N_NODES_MAX];

// ---------------------------------------------------------------------------
// Degree kernels
// ---------------------------------------------------------------------------
__global__ void deg_init_kernel(float* deg, int n) {
    int i = blockIdx.x * blockDim.x + threadIdx.x;
    if (i < n) deg[i] = 1.0f;  // self-loop contributes 1
}

__global__ void deg_acc_kernel(const int* __restrict__ dst, float* deg, int E) {
    int e = blockIdx.x * blockDim.x + threadIdx.x;
    if (e < E) atomicAdd(&deg[dst[e]], 1.0f);
}

__global__ void dinv_kernel(const float* __restrict__ deg, float* dinv, int n) {
    int i = blockIdx.x * blockDim.x + threadIdx.x;
    if (i < n) dinv[i] = rsqrtf(deg[i]);  // deg >= 1 always
}

// ---------------------------------------------------------------------------
// GEMM: h = x @ W, epilogue stores h and out = h * dinv^2 (self-loop term)
// Block: 256 threads, 32 rows per block. W kept transposed+padded in smem.
// ---------------------------------------------------------------------------
#define TILE_R 32
#define WPAD 132  // 128 + 4 pad (keeps LDS.128 phases conflict-free)

__global__ void __launch_bounds__(256, 2)
gemm_kernel(const float* __restrict__ x, const float* __restrict__ W,
            const float* __restrict__ dinv,
            float* __restrict__ out, float* __restrict__ h, int n) {
    extern __shared__ float sm[];
    float* WsT = sm;                 // [128 cols][WPAD]  (transposed W)
    float* Xs  = sm + FEAT * WPAD;   // [TILE_R][128]

    int tid = threadIdx.x;

    // Load W transposed: WsT[j][k] = W[k][j]
    for (int idx = tid; idx < FEAT * FEAT; idx += 256) {
        int k = idx >> 7, j = idx & 127;
        WsT[j * WPAD + k] = W[idx];
    }

    int r0 = blockIdx.x * TILE_R;
    for (int idx = tid; idx < TILE_R * FEAT; idx += 256) {
        int r = idx >> 7, k = idx & 127;
        int row = r0 + r;
        Xs[idx] = (row < n) ? x[(size_t)row * FEAT + k] : 0.0f;
    }
    __syncthreads();

    int col = tid & 127;
    int rg  = tid >> 7;  // 0 or 1; thread handles rows rg, rg+2, ..., rg+30

    float acc[16];
#pragma unroll
    for (int i = 0; i < 16; i++) acc[i] = 0.0f;

    const float4* wp = reinterpret_cast<const float4*>(WsT + col * WPAD);
#pragma unroll
    for (int q = 0; q < FEAT / 4; q++) {
        float4 wv = wp[q];
#pragma unroll
        for (int i = 0; i < 16; i++) {
            float4 xv = *reinterpret_cast<const float4*>(Xs + (rg + 2 * i) * FEAT + 4 * q);
            acc[i] = fmaf(wv.x, xv.x, acc[i]);
            acc[i] = fmaf(wv.y, xv.y, acc[i]);
            acc[i] = fmaf(wv.z, xv.z, acc[i]);
            acc[i] = fmaf(wv.w, xv.w, acc[i]);
        }
    }

#pragma unroll
    for (int i = 0; i < 16; i++) {
        int r = r0 + rg + 2 * i;
        if (r < n) {
            float hv = acc[i];
            size_t off = (size_t)r * FEAT + col;
            h[off] = hv;
            float di = dinv[r];
            out[off] = hv * di * di;  // self-loop message; bias added in gelu pass
        }
    }
}

// ---------------------------------------------------------------------------
// Edge scatter: one warp per edge. out[dst] += h[src] * dinv[src]*dinv[dst]
// Each lane handles one float4 (32 lanes * 4 floats = 128).
// ---------------------------------------------------------------------------
__global__ void __launch_bounds__(256)
scatter_kernel(const int* __restrict__ src, const int* __restrict__ dst,
               const float* __restrict__ dinv, const float* __restrict__ h,
               float* out, int E) {
    int e = blockIdx.x * 8 + (threadIdx.x >> 5);
    if (e >= E) return;
    int lane = threadIdx.x & 31;

    int s = __ldg(src + e);
    int d = __ldg(dst + e);
    float w = __ldg(dinv + s) * __ldg(dinv + d);

    float4 v = *reinterpret_cast<const float4*>(h + (size_t)s * FEAT + lane * 4);
    float a0 = v.x * w, a1 = v.y * w, a2 = v.z * w, a3 = v.w * w;
    float* p = out + (size_t)d * FEAT + lane * 4;
    asm volatile("red.global.add.v4.f32 [%0], {%1, %2, %3, %4};"
                 :: "l"(p), "f"(a0), "f"(a1), "f"(a2), "f"(a3)
                 : "memory");
}

// ---------------------------------------------------------------------------
// Epilogue: out = gelu(out + b), exact gelu = x * Phi(x)
// ---------------------------------------------------------------------------
__device__ __forceinline__ float gelu_exact(float v) {
    return v * normcdff(v);
}

__global__ void gelu_kernel(float* out, const float* __restrict__ b, int total4) {
    int i = blockIdx.x * blockDim.x + threadIdx.x;
    if (i >= total4) return;
    float4 v = reinterpret_cast<float4*>(out)[i];
    // 32 float4 per row of 128 -> bias float4 index = i % 32
    const float4 bb = *reinterpret_cast<const float4*>(b + ((i & 31) << 2));
    v.x = gelu_exact(v.x + bb.x);
    v.y = gelu_exact(v.y + bb.y);
    v.z = gelu_exact(v.z + bb.z);
    v.w = gelu_exact(v.w + bb.w);
    reinterpret_cast<float4*>(out)[i] = v;
}

// ---------------------------------------------------------------------------
// Launch
// ---------------------------------------------------------------------------
extern "C" void kernel_launch(void* const* d_in, const int* in_sizes, int n_in,
                              void* d_out, int out_size) {
    const float* x  = (const float*)d_in[0];
    const int*   ei = (const int*)d_in[1];
    const float* W  = (const float*)d_in[2];
    const float* b  = (const float*)d_in[3];
    float* out = (float*)d_out;

    int n = in_sizes[0] / FEAT;
    int E = in_sizes[1] / 2;
    const int* src = ei;
    const int* dst = ei + E;

    float *h_ptr, *deg_ptr, *dinv_ptr;
    cudaGetSymbolAddress((void**)&h_ptr, g_h);
    cudaGetSymbolAddress((void**)&deg_ptr, g_deg);
    cudaGetSymbolAddress((void**)&dinv_ptr, g_dinv);

    // degrees (can run before/parallel with GEMM; same stream keeps ordering)
    deg_init_kernel<<<(n + 255) / 256, 256>>>(deg_ptr, n);
    deg_acc_kernel<<<(E + 255) / 256, 256>>>(dst, deg_ptr, E);
    dinv_kernel<<<(n + 255) / 256, 256>>>(deg_ptr, dinv_ptr, n);

    // GEMM + self-loop init of out
    int smem_bytes = (FEAT * WPAD + TILE_R * FEAT) * (int)sizeof(float);
    cudaFuncSetAttribute(gemm_kernel, cudaFuncAttributeMaxDynamicSharedMemorySize, smem_bytes);
    int gemm_blocks = (n + TILE_R - 1) / TILE_R;
    gemm_kernel<<<gemm_blocks, 256, smem_bytes>>>(x, W, dinv_ptr, out, h_ptr, n);

    // edge aggregation
    int warps = E;
    int scat_blocks = (warps + 7) / 8;
    scatter_kernel<<<scat_blocks, 256>>>(src, dst, dinv_ptr, h_ptr, out, E);

    // bias + gelu
    int total4 = n * (FEAT / 4);
    gelu_kernel<<<(total4 + 255) / 256, 256>>>(out, b, total4);
}

// round 2
// speedup vs baseline: 1.2408x; 1.2408x over previous
#include <cuda_runtime.h>
#include <cuda_bf16.h>
#include <cstdint>

#define N_NODES_MAX 50000
#define FEAT 128
#define BM 64

// Scratch (allocation-free rule: __device__ globals)
__device__ float g_h[N_NODES_MAX * FEAT];
__device__ float g_deg[N_NODES_MAX];
__device__ float g_dinv[N_NODES_MAX];

// ---------------------------------------------------------------------------
// Degree kernels
// ---------------------------------------------------------------------------
__global__ void deg_init_kernel(float* deg, int n) {
    int i = blockIdx.x * blockDim.x + threadIdx.x;
    if (i < n) deg[i] = 1.0f;  // self-loop contributes 1
}

__global__ void deg_acc_kernel(const int* __restrict__ dst, float* deg, int E) {
    int e = blockIdx.x * blockDim.x + threadIdx.x;
    if (e < E) atomicAdd(&deg[dst[e]], 1.0f);
}

__global__ void dinv_kernel(const float* __restrict__ deg, float* dinv, int n) {
    int i = blockIdx.x * blockDim.x + threadIdx.x;
    if (i < n) dinv[i] = rsqrtf(deg[i]);  // deg >= 1 always
}

// ---------------------------------------------------------------------------
// Packed f32x2 helpers (Blackwell: doubles fp32 FMA throughput vs scalar FFMA)
// ---------------------------------------------------------------------------
__device__ __forceinline__ unsigned long long pack2(float lo, float hi) {
    unsigned long long r;
    asm("mov.b64 %0, {%1, %2};" : "=l"(r) : "f"(lo), "f"(hi));
    return r;
}
__device__ __forceinline__ void unpack2(unsigned long long v, float& lo, float& hi) {
    asm("mov.b64 {%0, %1}, %2;" : "=f"(lo), "=f"(hi) : "l"(v));
}
__device__ __forceinline__ void fma2(unsigned long long& d, unsigned long long a,
                                     unsigned long long b) {
    asm("fma.rn.f32x2 %0, %1, %2, %3;" : "=l"(d) : "l"(a), "l"(b), "l"(d));
}

// ---------------------------------------------------------------------------
// GEMM: h = x @ W, epilogue stores h and out = h * dinv^2 (self-loop term)
// Block tile 64x128, 256 threads, thread tile 4 rows x 8 cols (as 4x4 f32x2).
// Xs kept row-major: a-fragment reads are warp broadcasts (conflict-free).
// ---------------------------------------------------------------------------
__global__ void __launch_bounds__(256, 2)
gemm_kernel(const float* __restrict__ x, const float* __restrict__ W,
            const float* __restrict__ dinv,
            float* __restrict__ out, float* __restrict__ h, int n) {
    extern __shared__ float sm[];
    float* Ws = sm;              // [128][128]
    float* Xs = sm + FEAT * FEAT;  // [BM][128]

    int tid = threadIdx.x;

    // Load W [128][128]: 4096 float4, 16 per thread
    {
        const float4* s4 = reinterpret_cast<const float4*>(W);
        float4* d4 = reinterpret_cast<float4*>(Ws);
#pragma unroll
        for (int i = 0; i < 16; i++) d4[i * 256 + tid] = s4[i * 256 + tid];
    }

    // Load X tile [BM][128]: 2048 float4, 8 per thread, coalesced
    int r0blk = blockIdx.x * BM;
    {
        const float4* x4 = reinterpret_cast<const float4*>(x);
        float4* xs4 = reinterpret_cast<float4*>(Xs);
#pragma unroll
        for (int i = 0; i < 8; i++) {
            int idx = i * 256 + tid;       // 0..2047
            int r = idx >> 5;              // tile row
            int row = r0blk + r;
            float4 v = make_float4(0.f, 0.f, 0.f, 0.f);
            if (row < n) v = x4[(size_t)row * 32 + (idx & 31)];
            xs4[idx] = v;
        }
    }
    __syncthreads();

    int tx = tid & 15;   // column group
    int ty = tid >> 4;   // row group
    int c0 = tx * 8;
    int r0 = ty * 4;

    unsigned long long acc[4][4];
#pragma unroll
    for (int i = 0; i < 4; i++)
#pragma unroll
        for (int j = 0; j < 4; j++) acc[i][j] = 0ULL;  // {0.f, 0.f}

    const float* xrow = Xs + r0 * FEAT;

#pragma unroll 4
    for (int k = 0; k < FEAT; k++) {
        // b fragment: 8 cols = 4 f32x2, loaded as two LDS.128 (conflict-free)
        const ulonglong2 bA = *reinterpret_cast<const ulonglong2*>(Ws + k * FEAT + c0);
        const ulonglong2 bB = *reinterpret_cast<const ulonglong2*>(Ws + k * FEAT + c0 + 4);
        unsigned long long b[4] = {bA.x, bA.y, bB.x, bB.y};
#pragma unroll
        for (int i = 0; i < 4; i++) {
            float av = xrow[i * FEAT + k];       // warp-broadcast LDS
            unsigned long long aa = pack2(av, av);
#pragma unroll
            for (int j = 0; j < 4; j++) fma2(acc[i][j], aa, b[j]);
        }
    }

    // Epilogue: store h and out = h * dinv^2
#pragma unroll
    for (int i = 0; i < 4; i++) {
        int row = r0blk + r0 + i;
        if (row >= n) continue;
        float v[8];
#pragma unroll
        for (int j = 0; j < 4; j++) unpack2(acc[i][j], v[2 * j], v[2 * j + 1]);

        size_t off = (size_t)row * FEAT + c0;
        float4 h0 = make_float4(v[0], v[1], v[2], v[3]);
        float4 h1 = make_float4(v[4], v[5], v[6], v[7]);
        *reinterpret_cast<float4*>(h + off) = h0;
        *reinterpret_cast<float4*>(h + off + 4) = h1;

        float di = dinv[row];
        float d2 = di * di;
        float4 o0 = make_float4(v[0] * d2, v[1] * d2, v[2] * d2, v[3] * d2);
        float4 o1 = make_float4(v[4] * d2, v[5] * d2, v[6] * d2, v[7] * d2);
        *reinterpret_cast<float4*>(out + off) = o0;
        *reinterpret_cast<float4*>(out + off + 4) = o1;
    }
}

// ---------------------------------------------------------------------------
// Edge scatter: one warp per edge. out[dst] += h[src] * dinv[src]*dinv[dst]
// ---------------------------------------------------------------------------
__global__ void __launch_bounds__(256)
scatter_kernel(const int* __restrict__ src, const int* __restrict__ dst,
               const float* __restrict__ dinv, const float* __restrict__ h,
               float* out, int E) {
    int e = blockIdx.x * 8 + (threadIdx.x >> 5);
    if (e >= E) return;
    int lane = threadIdx.x & 31;

    int s = __ldg(src + e);
    int d = __ldg(dst + e);
    float w = __ldg(dinv + s) * __ldg(dinv + d);

    float4 v = *reinterpret_cast<const float4*>(h + (size_t)s * FEAT + lane * 4);
    float a0 = v.x * w, a1 = v.y * w, a2 = v.z * w, a3 = v.w * w;
    float* p = out + (size_t)d * FEAT + lane * 4;
    asm volatile("red.global.add.v4.f32 [%0], {%1, %2, %3, %4};"
                 :: "l"(p), "f"(a0), "f"(a1), "f"(a2), "f"(a3)
                 : "memory");
}

// ---------------------------------------------------------------------------
// Epilogue: out = gelu(out + b), exact gelu = x * Phi(x)
// ---------------------------------------------------------------------------
__device__ __forceinline__ float gelu_exact(float v) {
    return v * normcdff(v);
}

__global__ void gelu_kernel(float* out, const float* __restrict__ b, int total4) {
    int i = blockIdx.x * blockDim.x + threadIdx.x;
    if (i >= total4) return;
    float4 v = reinterpret_cast<float4*>(out)[i];
    const float4 bb = *reinterpret_cast<const float4*>(b + ((i & 31) << 2));
    v.x = gelu_exact(v.x + bb.x);
    v.y = gelu_exact(v.y + bb.y);
    v.z = gelu_exact(v.z + bb.z);
    v.w = gelu_exact(v.w + bb.w);
    reinterpret_cast<float4*>(out)[i] = v;
}

// ---------------------------------------------------------------------------
// Launch
// ---------------------------------------------------------------------------
extern "C" void kernel_launch(void* const* d_in, const int* in_sizes, int n_in,
                              void* d_out, int out_size) {
    const float* x  = (const float*)d_in[0];
    const int*   ei = (const int*)d_in[1];
    const float* W  = (const float*)d_in[2];
    const float* b  = (const float*)d_in[3];
    float* out = (float*)d_out;

    int n = in_sizes[0] / FEAT;
    int E = in_sizes[1] / 2;
    const int* src = ei;
    const int* dst = ei + E;

    float *h_ptr, *deg_ptr, *dinv_ptr;
    cudaGetSymbolAddress((void**)&h_ptr, g_h);
    cudaGetSymbolAddress((void**)&deg_ptr, g_deg);
    cudaGetSymbolAddress((void**)&dinv_ptr, g_dinv);

    // degrees
    deg_init_kernel<<<(n + 255) / 256, 256>>>(deg_ptr, n);
    deg_acc_kernel<<<(E + 255) / 256, 256>>>(dst, deg_ptr, E);
    dinv_kernel<<<(n + 255) / 256, 256>>>(deg_ptr, dinv_ptr, n);

    // GEMM + self-loop init of out
    int smem_bytes = (FEAT * FEAT + BM * FEAT) * (int)sizeof(float);  // 96 KB
    cudaFuncSetAttribute(gemm_kernel, cudaFuncAttributeMaxDynamicSharedMemorySize, smem_bytes);
    int gemm_blocks = (n + BM - 1) / BM;
    gemm_kernel<<<gemm_blocks, 256, smem_bytes>>>(x, W, dinv_ptr, out, h_ptr, n);

    // edge aggregation
    int scat_blocks = (E + 7) / 8;
    scatter_kernel<<<scat_blocks, 256>>>(src, dst, dinv_ptr, h_ptr, out, E);

    // bias + gelu
    int total4 = n * (FEAT / 4);
    gelu_kernel<<<(total4 + 255) / 256, 256>>>(out, b, total4);
}

// round 3
// speedup vs baseline: 1.4794x; 1.1923x over previous
#include <cuda_runtime.h>
#include <cuda_fp16.h>
#include <cstdint>

#define N_NODES_MAX 50000
#define FEAT 128
#define BM 64
#define WPADH 136  // half-elements per padded row: 272 B = 17*16B -> conflict-free ldmatrix, 16B aligned

// Scratch (allocation-free rule: __device__ globals)
__device__ __half g_h[N_NODES_MAX * FEAT];   // fp16 h for low-traffic gather
__device__ float  g_deg[N_NODES_MAX];
__device__ float  g_dinv[N_NODES_MAX];

// ---------------------------------------------------------------------------
// Degree kernels
// ---------------------------------------------------------------------------
__global__ void deg_init_kernel(float* deg, int n) {
    int i = blockIdx.x * blockDim.x + threadIdx.x;
    if (i < n) deg[i] = 1.0f;  // self-loop contributes 1
}

__global__ void deg_acc_kernel(const int* __restrict__ dst, float* deg, int E) {
    int e = blockIdx.x * blockDim.x + threadIdx.x;
    if (e < E) atomicAdd(&deg[dst[e]], 1.0f);  // compiles to REDG (no return use)
}

__global__ void dinv_kernel(const float* __restrict__ deg, float* dinv, int n) {
    int i = blockIdx.x * blockDim.x + threadIdx.x;
    if (i < n) dinv[i] = rsqrtf(deg[i]);  // deg >= 1 always
}

// ---------------------------------------------------------------------------
// Tensor-core helpers (legacy mma.sync path, valid on sm_100a)
// ---------------------------------------------------------------------------
__device__ __forceinline__ uint32_t smem_u32(const void* p) {
    return (uint32_t)__cvta_generic_to_shared(p);
}

__device__ __forceinline__ void ldmatrix_x4(uint32_t& r0, uint32_t& r1,
                                            uint32_t& r2, uint32_t& r3, uint32_t addr) {
    asm volatile("ldmatrix.sync.aligned.m8n8.x4.shared.b16 {%0,%1,%2,%3}, [%4];"
                 : "=r"(r0), "=r"(r1), "=r"(r2), "=r"(r3) : "r"(addr));
}

__device__ __forceinline__ void ldmatrix_x2_trans(uint32_t& r0, uint32_t& r1, uint32_t addr) {
    asm volatile("ldmatrix.sync.aligned.m8n8.x2.trans.shared.b16 {%0,%1}, [%2];"
                 : "=r"(r0), "=r"(r1) : "r"(addr));
}

__device__ __forceinline__ void mma16816(float* c, uint32_t a0, uint32_t a1,
                                         uint32_t a2, uint32_t a3,
                                         uint32_t b0, uint32_t b1) {
    asm volatile(
        "mma.sync.aligned.m16n8k16.row.col.f32.f16.f16.f32 "
        "{%0,%1,%2,%3}, {%4,%5,%6,%7}, {%8,%9}, {%0,%1,%2,%3};"
        : "+f"(c[0]), "+f"(c[1]), "+f"(c[2]), "+f"(c[3])
        : "r"(a0), "r"(a1), "r"(a2), "r"(a3), "r"(b0), "r"(b1));
}

// ---------------------------------------------------------------------------
// GEMM: h = x @ W (fp16 inputs converted on load, fp32 accumulate).
// Block tile 64x128 over 8 warps (4 row-groups x 2 col-groups), k-loop of 8.
// Epilogue: h (fp16) and out = h_fp32 * dinv^2 (self-loop term).
// ---------------------------------------------------------------------------
__global__ void __launch_bounds__(256)
gemm_kernel(const float* __restrict__ x, const float* __restrict__ W,
            const float* __restrict__ dinv,
            float* __restrict__ out, __half* __restrict__ h, int n) {
    extern __shared__ __half sh[];
    __half* Wh = sh;                    // [128][WPADH]
    __half* Xh = sh + FEAT * WPADH;     // [BM][WPADH]

    int tid = threadIdx.x;
    int r0blk = blockIdx.x * BM;

    // Stage W (fp32 -> fp16): 128x128 = 4096 float4 loads
    {
        const float4* w4 = reinterpret_cast<const float4*>(W);
#pragma unroll
        for (int i = 0; i < 16; i++) {
            int idx = i * 256 + tid;          // 0..4095
            int row = idx >> 5, c4 = idx & 31;
            float4 v = w4[idx];
            __half2 p0 = __floats2half2_rn(v.x, v.y);
            __half2 p1 = __floats2half2_rn(v.z, v.w);
            __half2* d = reinterpret_cast<__half2*>(Wh + row * WPADH + c4 * 4);
            d[0] = p0; d[1] = p1;
        }
    }
    // Stage X tile (fp32 -> fp16): 64x128 = 2048 float4 loads
    {
        const float4* x4 = reinterpret_cast<const float4*>(x);
#pragma unroll
        for (int i = 0; i < 8; i++) {
            int idx = i * 256 + tid;          // 0..2047
            int r = idx >> 5, c4 = idx & 31;
            int row = r0blk + r;
            float4 v = make_float4(0.f, 0.f, 0.f, 0.f);
            if (row < n) v = x4[(size_t)row * 32 + c4];
            __half2 p0 = __floats2half2_rn(v.x, v.y);
            __half2 p1 = __floats2half2_rn(v.z, v.w);
            __half2* d = reinterpret_cast<__half2*>(Xh + r * WPADH + c4 * 4);
            d[0] = p0; d[1] = p1;
        }
    }
    __syncthreads();

    int w  = tid >> 5;
    int lane = tid & 31;
    int wr = w & 3;        // row group: rows wr*16 .. +15
    int wc = w >> 2;       // col group: cols wc*64 .. +63 (8 n-tiles)

    float acc[8][4];
#pragma unroll
    for (int nt = 0; nt < 8; nt++)
#pragma unroll
        for (int j = 0; j < 4; j++) acc[nt][j] = 0.f;

    // ldmatrix lane-address precompute
    int t  = lane >> 3, r8 = lane & 7;
    int a_row = wr * 16 + (t & 1) * 8 + r8;    // A tile order: (m0-7,k0-7),(m8-15,k0-7),(m0-7,k8+),(m8-15,k8+)
    int a_kof = (t >> 1) * 8;
    uint32_t a_base = smem_u32(Xh + a_row * WPADH + a_kof);
    int bt = (lane >> 3) & 1;                  // B tiles: (k0-7,n),(k8-15,n); lanes>=16 mirror lanes 0-15
    uint32_t b_base = smem_u32(Wh + (bt * 8 + r8) * WPADH + wc * 64);

#pragma unroll
    for (int kk = 0; kk < 8; kk++) {
        uint32_t a0, a1, a2, a3;
        ldmatrix_x4(a0, a1, a2, a3, a_base + kk * 16 * sizeof(__half));
        uint32_t brow = b_base + kk * 16 * WPADH * sizeof(__half);
#pragma unroll
        for (int nt = 0; nt < 8; nt++) {
            uint32_t b0, b1;
            ldmatrix_x2_trans(b0, b1, brow + nt * 8 * sizeof(__half));
            mma16816(acc[nt], a0, a1, a2, a3, b0, b1);
        }
    }

    // Epilogue
    int group = lane >> 2, tg = lane & 3;
    int r_lo = r0blk + wr * 16 + group;
    int r_hi = r_lo + 8;
    float d2_lo = 0.f, d2_hi = 0.f;
    if (r_lo < n) { float di = dinv[r_lo]; d2_lo = di * di; }
    if (r_hi < n) { float di = dinv[r_hi]; d2_hi = di * di; }

#pragma unroll
    for (int nt = 0; nt < 8; nt++) {
        int col = wc * 64 + nt * 8 + tg * 2;
        if (r_lo < n) {
            size_t off = (size_t)r_lo * FEAT + col;
            *reinterpret_cast<__half2*>(h + off) = __floats2half2_rn(acc[nt][0], acc[nt][1]);
            *reinterpret_cast<float2*>(out + off) = make_float2(acc[nt][0] * d2_lo, acc[nt][1] * d2_lo);
        }
        if (r_hi < n) {
            size_t off = (size_t)r_hi * FEAT + col;
            *reinterpret_cast<__half2*>(h + off) = __floats2half2_rn(acc[nt][2], acc[nt][3]);
            *reinterpret_cast<float2*>(out + off) = make_float2(acc[nt][2] * d2_hi, acc[nt][3] * d2_hi);
        }
    }
}

// ---------------------------------------------------------------------------
// Edge scatter: 16 lanes per edge. out[dst] += fp32(h16[src]) * dinv[s]*dinv[d]
// Each lane handles 8 halves (uint4 = 16B read) -> 2x red.global.add.v4.f32
// ---------------------------------------------------------------------------
__global__ void __launch_bounds__(256)
scatter_kernel(const int* __restrict__ src, const int* __restrict__ dst,
               const float* __restrict__ dinv, const __half* __restrict__ h,
               float* out, int E) {
    int e = blockIdx.x * 16 + (threadIdx.x >> 4);
    if (e >= E) return;
    int lane = threadIdx.x & 15;

    int s = __ldg(src + e);
    int d = __ldg(dst + e);
    float w = __ldg(dinv + s) * __ldg(dinv + d);

    const uint4 v = *(reinterpret_cast<const uint4*>(h + (size_t)s * FEAT) + lane);
    const __half2* hp = reinterpret_cast<const __half2*>(&v);
    float2 f0 = __half22float2(hp[0]);
    float2 f1 = __half22float2(hp[1]);
    float2 f2 = __half22float2(hp[2]);
    float2 f3 = __half22float2(hp[3]);

    float* p = out + (size_t)d * FEAT + lane * 8;
    asm volatile("red.global.add.v4.f32 [%0], {%1, %2, %3, %4};"
                 :: "l"(p), "f"(f0.x * w), "f"(f0.y * w), "f"(f1.x * w), "f"(f1.y * w)
                 : "memory");
    asm volatile("red.global.add.v4.f32 [%0], {%1, %2, %3, %4};"
                 :: "l"(p + 4), "f"(f2.x * w), "f"(f2.y * w), "f"(f3.x * w), "f"(f3.y * w)
                 : "memory");
}

// ---------------------------------------------------------------------------
// Epilogue: out = gelu(out + b), exact gelu = x * Phi(x)
// ---------------------------------------------------------------------------
__device__ __forceinline__ float gelu_exact(float v) {
    return v * normcdff(v);
}

__global__ void gelu_kernel(float* out, const float* __restrict__ b, int total4) {
    int i = blockIdx.x * blockDim.x + threadIdx.x;
    if (i >= total4) return;
    float4 v = reinterpret_cast<float4*>(out)[i];
    const float4 bb = *reinterpret_cast<const float4*>(b + ((i & 31) << 2));
    v.x = gelu_exact(v.x + bb.x);
    v.y = gelu_exact(v.y + bb.y);
    v.z = gelu_exact(v.z + bb.z);
    v.w = gelu_exact(v.w + bb.w);
    reinterpret_cast<float4*>(out)[i] = v;
}

// ---------------------------------------------------------------------------
// Launch
// ---------------------------------------------------------------------------
extern "C" void kernel_launch(void* const* d_in, const int* in_sizes, int n_in,
                              void* d_out, int out_size) {
    const float* x  = (const float*)d_in[0];
    const int*   ei = (const int*)d_in[1];
    const float* W  = (const float*)d_in[2];
    const float* b  = (const float*)d_in[3];
    float* out = (float*)d_out;

    int n = in_sizes[0] / FEAT;
    int E = in_sizes[1] / 2;
    const int* src = ei;
    const int* dst = ei + E;

    __half* h_ptr; float *deg_ptr, *dinv_ptr;
    cudaGetSymbolAddress((void**)&h_ptr, g_h);
    cudaGetSymbolAddress((void**)&deg_ptr, g_deg);
    cudaGetSymbolAddress((void**)&dinv_ptr, g_dinv);

    // degrees
    deg_init_kernel<<<(n + 255) / 256, 256>>>(deg_ptr, n);
    deg_acc_kernel<<<(E + 255) / 256, 256>>>(dst, deg_ptr, E);
    dinv_kernel<<<(n + 255) / 256, 256>>>(deg_ptr, dinv_ptr, n);

    // GEMM + self-loop init of out
    int smem_bytes = (FEAT + BM) * WPADH * (int)sizeof(__half);  // ~52 KB
    cudaFuncSetAttribute(gemm_kernel, cudaFuncAttributeMaxDynamicSharedMemorySize, smem_bytes);
    int gemm_blocks = (n + BM - 1) / BM;
    gemm_kernel<<<gemm_blocks, 256, smem_bytes>>>(x, W, dinv_ptr, out, h_ptr, n);

    // edge aggregation (16 edges per 256-thread block)
    int scat_blocks = (E + 15) / 16;
    scatter_kernel<<<scat_blocks, 256>>>(src, dst, dinv_ptr, h_ptr, out, E);

    // bias + gelu
    int total4 = n * (FEAT / 4);
    gelu_kernel<<<(total4 + 255) / 256, 256>>>(out, b, total4);
}

// round 4
// speedup vs baseline: 3.0229x; 2.0434x over previous
#include <cuda_runtime.h>
#include <cuda_fp16.h>
#include <cstdint>

#define N_NODES_MAX 50000
#define N_EDGES_MAX 800000
#define FEAT 128
#define BM 64
#define WPADH 136  // padded half row: 272 B = 17*16B -> conflict-free ldmatrix
#define CAP 64     // per-node bucket capacity (deg ~Poisson(16); overflow handled)

// Scratch (allocation-free rule: __device__ globals)
__device__ __half g_h[N_NODES_MAX * FEAT];      // fp16 h for low-traffic gather
__device__ float  g_dinv[N_NODES_MAX];
__device__ int    g_cnt[N_NODES_MAX];
__device__ int    g_list[N_NODES_MAX * CAP];    // bucketed src indices (12.8 MB)
__device__ int    g_ovf[N_EDGES_MAX];           // overflow edge ids
__device__ int    g_ovf_cnt;

// ---------------------------------------------------------------------------
// Reset counters (every launch: determinism across graph replays)
// ---------------------------------------------------------------------------
__global__ void zero_kernel(int* cnt, int* ovf_cnt, int n) {
    int i = blockIdx.x * blockDim.x + threadIdx.x;
    if (i < n) cnt[i] = 0;
    if (i == 0) *ovf_cnt = 0;
}

// ---------------------------------------------------------------------------
// Fill buckets: histogram + bin in one pass
// ---------------------------------------------------------------------------
__global__ void fill_kernel(const int* __restrict__ src, const int* __restrict__ dst,
                            int* cnt, int* list, int* ovf, int* ovf_cnt, int E) {
    int e = blockIdx.x * blockDim.x + threadIdx.x;
    if (e >= E) return;
    int d = __ldg(dst + e);
    int p = atomicAdd(&cnt[d], 1);
    if (p < CAP) list[d * CAP + p] = __ldg(src + e);
    else         ovf[atomicAdd(ovf_cnt, 1)] = e;
}

__global__ void dinv_kernel(const int* __restrict__ cnt, float* dinv, int n) {
    int i = blockIdx.x * blockDim.x + threadIdx.x;
    if (i < n) dinv[i] = rsqrtf((float)(cnt[i] + 1));  // +1 self-loop
}

// ---------------------------------------------------------------------------
// Tensor-core helpers
// ---------------------------------------------------------------------------
__device__ __forceinline__ uint32_t smem_u32(const void* p) {
    return (uint32_t)__cvta_generic_to_shared(p);
}
__device__ __forceinline__ void ldmatrix_x4(uint32_t& r0, uint32_t& r1,
                                            uint32_t& r2, uint32_t& r3, uint32_t addr) {
    asm volatile("ldmatrix.sync.aligned.m8n8.x4.shared.b16 {%0,%1,%2,%3}, [%4];"
                 : "=r"(r0), "=r"(r1), "=r"(r2), "=r"(r3) : "r"(addr));
}
__device__ __forceinline__ void ldmatrix_x2_trans(uint32_t& r0, uint32_t& r1, uint32_t addr) {
    asm volatile("ldmatrix.sync.aligned.m8n8.x2.trans.shared.b16 {%0,%1}, [%2];"
                 : "=r"(r0), "=r"(r1) : "r"(addr));
}
__device__ __forceinline__ void mma16816(float* c, uint32_t a0, uint32_t a1,
                                         uint32_t a2, uint32_t a3,
                                         uint32_t b0, uint32_t b1) {
    asm volatile(
        "mma.sync.aligned.m16n8k16.row.col.f32.f16.f16.f32 "
        "{%0,%1,%2,%3}, {%4,%5,%6,%7}, {%8,%9}, {%0,%1,%2,%3};"
        : "+f"(c[0]), "+f"(c[1]), "+f"(c[2]), "+f"(c[3])
        : "r"(a0), "r"(a1), "r"(a2), "r"(a3), "r"(b0), "r"(b1));
}

// ---------------------------------------------------------------------------
// GEMM: h = x @ W (fp16 in, fp32 acc). out = h_fp32 * dinv^2 (self-loop term)
// ---------------------------------------------------------------------------
__global__ void __launch_bounds__(256)
gemm_kernel(const float* __restrict__ x, const float* __restrict__ W,
            const float* __restrict__ dinv,
            float* __restrict__ out, __half* __restrict__ h, int n) {
    extern __shared__ __half sh[];
    __half* Wh = sh;                    // [128][WPADH]
    __half* Xh = sh + FEAT * WPADH;     // [BM][WPADH]

    int tid = threadIdx.x;
    int r0blk = blockIdx.x * BM;

    {
        const float4* w4 = reinterpret_cast<const float4*>(W);
#pragma unroll
        for (int i = 0; i < 16; i++) {
            int idx = i * 256 + tid;
            int row = idx >> 5, c4 = idx & 31;
            float4 v = w4[idx];
            __half2* d = reinterpret_cast<__half2*>(Wh + row * WPADH + c4 * 4);
            d[0] = __floats2half2_rn(v.x, v.y);
            d[1] = __floats2half2_rn(v.z, v.w);
        }
    }
    {
        const float4* x4 = reinterpret_cast<const float4*>(x);
#pragma unroll
        for (int i = 0; i < 8; i++) {
            int idx = i * 256 + tid;
            int r = idx >> 5, c4 = idx & 31;
            int row = r0blk + r;
            float4 v = make_float4(0.f, 0.f, 0.f, 0.f);
            if (row < n) v = x4[(size_t)row * 32 + c4];
            __half2* d = reinterpret_cast<__half2*>(Xh + r * WPADH + c4 * 4);
            d[0] = __floats2half2_rn(v.x, v.y);
            d[1] = __floats2half2_rn(v.z, v.w);
        }
    }
    __syncthreads();

    int w = tid >> 5, lane = tid & 31;
    int wr = w & 3, wc = w >> 2;

    float acc[8][4];
#pragma unroll
    for (int nt = 0; nt < 8; nt++)
#pragma unroll
        for (int j = 0; j < 4; j++) acc[nt][j] = 0.f;

    int t = lane >> 3, r8 = lane & 7;
    int a_row = wr * 16 + (t & 1) * 8 + r8;
    int a_kof = (t >> 1) * 8;
    uint32_t a_base = smem_u32(Xh + a_row * WPADH + a_kof);
    int bt = (lane >> 3) & 1;
    uint32_t b_base = smem_u32(Wh + (bt * 8 + r8) * WPADH + wc * 64);

#pragma unroll
    for (int kk = 0; kk < 8; kk++) {
        uint32_t a0, a1, a2, a3;
        ldmatrix_x4(a0, a1, a2, a3, a_base + kk * 16 * sizeof(__half));
        uint32_t brow = b_base + kk * 16 * WPADH * sizeof(__half);
#pragma unroll
        for (int nt = 0; nt < 8; nt++) {
            uint32_t b0, b1;
            ldmatrix_x2_trans(b0, b1, brow + nt * 8 * sizeof(__half));
            mma16816(acc[nt], a0, a1, a2, a3, b0, b1);
        }
    }

    int group = lane >> 2, tg = lane & 3;
    int r_lo = r0blk + wr * 16 + group;
    int r_hi = r_lo + 8;
    float d2_lo = 0.f, d2_hi = 0.f;
    if (r_lo < n) { float di = dinv[r_lo]; d2_lo = di * di; }
    if (r_hi < n) { float di = dinv[r_hi]; d2_hi = di * di; }

#pragma unroll
    for (int nt = 0; nt < 8; nt++) {
        int col = wc * 64 + nt * 8 + tg * 2;
        if (r_lo < n) {
            size_t off = (size_t)r_lo * FEAT + col;
            *reinterpret_cast<__half2*>(h + off) = __floats2half2_rn(acc[nt][0], acc[nt][1]);
            *reinterpret_cast<float2*>(out + off) = make_float2(acc[nt][0] * d2_lo, acc[nt][1] * d2_lo);
        }
        if (r_hi < n) {
            size_t off = (size_t)r_hi * FEAT + col;
            *reinterpret_cast<__half2*>(h + off) = __floats2half2_rn(acc[nt][2], acc[nt][3]);
            *reinterpret_cast<float2*>(out + off) = make_float2(acc[nt][2] * d2_hi, acc[nt][3] * d2_hi);
        }
    }
}

// ---------------------------------------------------------------------------
// Overflow scatter (rarely/never runs): old-style RED path for edges whose
// bucket was full. Must run after gemm (needs h, adds into out) and before
// gather (which reads out as the accumulation base).
// ---------------------------------------------------------------------------
__global__ void __launch_bounds__(256)
ovf_scatter_kernel(const int* __restrict__ src, const int* __restrict__ dst,
                   const int* __restrict__ ovf, const int* __restrict__ ovf_cnt,
                   const float* __restrict__ dinv, const __half* __restrict__ h,
                   float* out) {
    int m = *ovf_cnt;
    int lane = threadIdx.x & 15;
    for (int i = blockIdx.x * 16 + (threadIdx.x >> 4); i < m; i += gridDim.x * 16) {
        int e = ovf[i];
        int s = __ldg(src + e);
        int d = __ldg(dst + e);
        float w = __ldg(dinv + s) * __ldg(dinv + d);
        const uint4 v = *(reinterpret_cast<const uint4*>(h + (size_t)s * FEAT) + lane);
        const __half2* hp = reinterpret_cast<const __half2*>(&v);
        float2 f0 = __half22float2(hp[0]), f1 = __half22float2(hp[1]);
        float2 f2 = __half22float2(hp[2]), f3 = __half22float2(hp[3]);
        float* p = out + (size_t)d * FEAT + lane * 8;
        asm volatile("red.global.add.v4.f32 [%0], {%1, %2, %3, %4};"
                     :: "l"(p), "f"(f0.x * w), "f"(f0.y * w), "f"(f1.x * w), "f"(f1.y * w) : "memory");
        asm volatile("red.global.add.v4.f32 [%0], {%1, %2, %3, %4};"
                     :: "l"(p + 4), "f"(f2.x * w), "f"(f2.y * w), "f"(f3.x * w), "f"(f3.y * w) : "memory");
    }
}

// ---------------------------------------------------------------------------
// Gather: one warp per node. acc = out_row (self-loop + overflow), then
// sum over bucketed in-edges, then bias + exact gelu, single store.
// ---------------------------------------------------------------------------
__device__ __forceinline__ float gelu_exact(float v) { return v * normcdff(v); }

__global__ void __launch_bounds__(256)
gather_kernel(const int* __restrict__ cnt, const int* __restrict__ list,
              const float* __restrict__ dinv, const __half* __restrict__ h,
              const float* __restrict__ b, float* out, int n) {
    int node = blockIdx.x * 8 + (threadIdx.x >> 5);
    if (node >= n) return;
    int lane = threadIdx.x & 31;

    int m = cnt[node];
    if (m > CAP) m = CAP;
    float dd = dinv[node];

    float4 acc = *(reinterpret_cast<const float4*>(out + (size_t)node * FEAT) + lane);
    const int* lp = list + (size_t)node * CAP;

    for (int base = 0; base < m; base += 32) {
        int idx = base + lane;
        int s = 0; float ws = 0.f;
        if (idx < m) { s = lp[idx]; ws = __ldg(dinv + s); }
        int cnum = m - base; if (cnum > 32) cnum = 32;
        for (int j = 0; j < cnum; j++) {
            int   sj = __shfl_sync(0xFFFFFFFFu, s,  j);
            float wj = __shfl_sync(0xFFFFFFFFu, ws, j) * dd;
            uint2 hv = *(reinterpret_cast<const uint2*>(h + (size_t)sj * FEAT) + lane);
            float2 fa = __half22float2(*reinterpret_cast<const __half2*>(&hv.x));
            float2 fb = __half22float2(*reinterpret_cast<const __half2*>(&hv.y));
            acc.x = fmaf(wj, fa.x, acc.x);
            acc.y = fmaf(wj, fa.y, acc.y);
            acc.z = fmaf(wj, fb.x, acc.z);
            acc.w = fmaf(wj, fb.y, acc.w);
        }
    }

    float4 bb = *(reinterpret_cast<const float4*>(b) + lane);
    acc.x = gelu_exact(acc.x + bb.x);
    acc.y = gelu_exact(acc.y + bb.y);
    acc.z = gelu_exact(acc.z + bb.z);
    acc.w = gelu_exact(acc.w + bb.w);
    *(reinterpret_cast<float4*>(out + (size_t)node * FEAT) + lane) = acc;
}

// ---------------------------------------------------------------------------
// Launch
// ---------------------------------------------------------------------------
extern "C" void kernel_launch(void* const* d_in, const int* in_sizes, int n_in,
                              void* d_out, int out_size) {
    const float* x  = (const float*)d_in[0];
    const int*   ei = (const int*)d_in[1];
    const float* W  = (const float*)d_in[2];
    const float* b  = (const float*)d_in[3];
    float* out = (float*)d_out;

    int n = in_sizes[0] / FEAT;
    int E = in_sizes[1] / 2;
    const int* src = ei;
    const int* dst = ei + E;

    __half* h_ptr; float* dinv_ptr; int *cnt_ptr, *list_ptr, *ovf_ptr, *ovfc_ptr;
    cudaGetSymbolAddress((void**)&h_ptr, g_h);
    cudaGetSymbolAddress((void**)&dinv_ptr, g_dinv);
    cudaGetSymbolAddress((void**)&cnt_ptr, g_cnt);
    cudaGetSymbolAddress((void**)&list_ptr, g_list);
    cudaGetSymbolAddress((void**)&ovf_ptr, g_ovf);
    cudaGetSymbolAddress((void**)&ovfc_ptr, g_ovf_cnt);

    zero_kernel<<<(n + 255) / 256, 256>>>(cnt_ptr, ovfc_ptr, n);
    fill_kernel<<<(E + 255) / 256, 256>>>(src, dst, cnt_ptr, list_ptr, ovf_ptr, ovfc_ptr, E);
    dinv_kernel<<<(n + 255) / 256, 256>>>(cnt_ptr, dinv_ptr, n);

    int smem_bytes = (FEAT + BM) * WPADH * (int)sizeof(__half);
    cudaFuncSetAttribute(gemm_kernel, cudaFuncAttributeMaxDynamicSharedMemorySize, smem_bytes);
    gemm_kernel<<<(n + BM - 1) / BM, 256, smem_bytes>>>(x, W, dinv_ptr, out, h_ptr, n);

    ovf_scatter_kernel<<<64, 256>>>(src, dst, ovf_ptr, ovfc_ptr, dinv_ptr, h_ptr, out);

    gather_kernel<<<(n + 7) / 8, 256>>>(cnt_ptr, list_ptr, dinv_ptr, h_ptr, b, out, n);
}

// round 5
// speedup vs baseline: 3.3614x; 1.1120x over previous
#include <cuda_runtime.h>
#include <cuda_fp16.h>
#include <cstdint>

#define N_NODES_MAX 50000
#define N_EDGES_MAX 800000
#define FEAT 128
#define BM 128
#define WPADH 136  // padded half row: 272 B = 17*16B -> conflict-free ldmatrix
#define CAP 64     // per-node bucket capacity (deg ~Poisson(16); overflow handled)

// Scratch (allocation-free rule: __device__ globals)
__device__ __half g_h[N_NODES_MAX * FEAT];      // h' = (x@W) * dinv[row], fp16
__device__ __half g_wh[FEAT * FEAT];            // fp16 W (converted once)
__device__ float  g_dinv[N_NODES_MAX];
__device__ int    g_cnt[N_NODES_MAX];
__device__ int    g_list[N_NODES_MAX * CAP];    // bucketed src indices
__device__ int    g_ovf[N_EDGES_MAX];           // overflow edge ids
__device__ int    g_ovf_cnt;
__device__ float  g_extra[N_NODES_MAX * FEAT];  // overflow accumulation (lazily zeroed)

// ---------------------------------------------------------------------------
__global__ void zero_kernel(int* cnt, int* ovf_cnt, int n) {
    int i = blockIdx.x * blockDim.x + threadIdx.x;
    if (i < n) cnt[i] = 0;
    if (i == 0) *ovf_cnt = 0;
}

__global__ void wconv_kernel(const float* __restrict__ W, __half* __restrict__ wh) {
    int i = blockIdx.x * blockDim.x + threadIdx.x;  // 4096 float4
    if (i >= FEAT * FEAT / 4) return;
    float4 v = reinterpret_cast<const float4*>(W)[i];
    __half2* d = reinterpret_cast<__half2*>(wh + i * 4);
    d[0] = __floats2half2_rn(v.x, v.y);
    d[1] = __floats2half2_rn(v.z, v.w);
}

__global__ void fill_kernel(const int* __restrict__ src, const int* __restrict__ dst,
                            int* cnt, int* list, int* ovf, int* ovf_cnt, int E) {
    int e = blockIdx.x * blockDim.x + threadIdx.x;
    if (e >= E) return;
    int d = __ldg(dst + e);
    int p = atomicAdd(&cnt[d], 1);
    if (p < CAP) list[d * CAP + p] = __ldg(src + e);
    else         ovf[atomicAdd(ovf_cnt, 1)] = e;
}

__global__ void dinv_kernel(const int* __restrict__ cnt, float* dinv, int n) {
    int i = blockIdx.x * blockDim.x + threadIdx.x;
    if (i < n) dinv[i] = rsqrtf((float)(cnt[i] + 1));  // +1 self-loop
}

// ---------------------------------------------------------------------------
// Tensor-core helpers
// ---------------------------------------------------------------------------
__device__ __forceinline__ uint32_t smem_u32(const void* p) {
    return (uint32_t)__cvta_generic_to_shared(p);
}
__device__ __forceinline__ void ldmatrix_x4(uint32_t& r0, uint32_t& r1,
                                            uint32_t& r2, uint32_t& r3, uint32_t addr) {
    asm volatile("ldmatrix.sync.aligned.m8n8.x4.shared.b16 {%0,%1,%2,%3}, [%4];"
                 : "=r"(r0), "=r"(r1), "=r"(r2), "=r"(r3) : "r"(addr));
}
__device__ __forceinline__ void ldmatrix_x2_trans(uint32_t& r0, uint32_t& r1, uint32_t addr) {
    asm volatile("ldmatrix.sync.aligned.m8n8.x2.trans.shared.b16 {%0,%1}, [%2];"
                 : "=r"(r0), "=r"(r1) : "r"(addr));
}
__device__ __forceinline__ void mma16816(float* c, uint32_t a0, uint32_t a1,
                                         uint32_t a2, uint32_t a3,
                                         uint32_t b0, uint32_t b1) {
    asm volatile(
        "mma.sync.aligned.m16n8k16.row.col.f32.f16.f16.f32 "
        "{%0,%1,%2,%3}, {%4,%5,%6,%7}, {%8,%9}, {%0,%1,%2,%3};"
        : "+f"(c[0]), "+f"(c[1]), "+f"(c[2]), "+f"(c[3])
        : "r"(a0), "r"(a1), "r"(a2), "r"(a3), "r"(b0), "r"(b1));
}

// ---------------------------------------------------------------------------
// GEMM: h' = (x @ W) * dinv[row], fp16 out. Tile 128x128, 512 threads.
// ---------------------------------------------------------------------------
__global__ void __launch_bounds__(512)
gemm_kernel(const float* __restrict__ x, const __half* __restrict__ wh,
            const float* __restrict__ dinv, __half* __restrict__ h, int n) {
    extern __shared__ __half sh[];
    __half* Wh = sh;                    // [128][WPADH]
    __half* Xh = sh + FEAT * WPADH;     // [BM][WPADH]

    int tid = threadIdx.x;
    int r0blk = blockIdx.x * BM;

    // Stage W (already fp16): 2048 uint4
    {
        const uint4* w4 = reinterpret_cast<const uint4*>(wh);
#pragma unroll
        for (int i = 0; i < 4; i++) {
            int idx = i * 512 + tid;          // 0..2047
            int r = idx >> 4, c = idx & 15;
            *reinterpret_cast<uint4*>(Wh + r * WPADH + c * 8) = w4[idx];
        }
    }
    // Stage X tile (fp32 -> fp16): 128x32 float4 = 4096
    {
        const float4* x4 = reinterpret_cast<const float4*>(x);
#pragma unroll
        for (int i = 0; i < 8; i++) {
            int idx = i * 512 + tid;          // 0..4095
            int r = idx >> 5, c4 = idx & 31;
            int row = r0blk + r;
            float4 v = make_float4(0.f, 0.f, 0.f, 0.f);
            if (row < n) v = x4[(size_t)row * 32 + c4];
            __half2* d = reinterpret_cast<__half2*>(Xh + r * WPADH + c4 * 4);
            d[0] = __floats2half2_rn(v.x, v.y);
            d[1] = __floats2half2_rn(v.z, v.w);
        }
    }
    __syncthreads();

    int w = tid >> 5, lane = tid & 31;
    int wr = w & 7;        // 8 row groups of 16
    int wc = w >> 3;       // 2 col groups of 64

    float acc[8][4];
#pragma unroll
    for (int nt = 0; nt < 8; nt++)
#pragma unroll
        for (int j = 0; j < 4; j++) acc[nt][j] = 0.f;

    int t = lane >> 3, r8 = lane & 7;
    int a_row = wr * 16 + (t & 1) * 8 + r8;
    int a_kof = (t >> 1) * 8;
    uint32_t a_base = smem_u32(Xh + a_row * WPADH + a_kof);
    int bt = (lane >> 3) & 1;
    uint32_t b_base = smem_u32(Wh + (bt * 8 + r8) * WPADH + wc * 64);

#pragma unroll
    for (int kk = 0; kk < 8; kk++) {
        uint32_t a0, a1, a2, a3;
        ldmatrix_x4(a0, a1, a2, a3, a_base + kk * 16 * sizeof(__half));
        uint32_t brow = b_base + kk * 16 * WPADH * sizeof(__half);
#pragma unroll
        for (int nt = 0; nt < 8; nt++) {
            uint32_t b0, b1;
            ldmatrix_x2_trans(b0, b1, brow + nt * 8 * sizeof(__half));
            mma16816(acc[nt], a0, a1, a2, a3, b0, b1);
        }
    }

    int group = lane >> 2, tg = lane & 3;
    int r_lo = r0blk + wr * 16 + group;
    int r_hi = r_lo + 8;
    float di_lo = (r_lo < n) ? dinv[r_lo] : 0.f;
    float di_hi = (r_hi < n) ? dinv[r_hi] : 0.f;

#pragma unroll
    for (int nt = 0; nt < 8; nt++) {
        int col = wc * 64 + nt * 8 + tg * 2;
        if (r_lo < n)
            *reinterpret_cast<__half2*>(h + (size_t)r_lo * FEAT + col) =
                __floats2half2_rn(acc[nt][0] * di_lo, acc[nt][1] * di_lo);
        if (r_hi < n)
            *reinterpret_cast<__half2*>(h + (size_t)r_hi * FEAT + col) =
                __floats2half2_rn(acc[nt][2] * di_hi, acc[nt][3] * di_hi);
    }
}

// ---------------------------------------------------------------------------
// Overflow path (never runs for this graph; correctness insurance).
// ---------------------------------------------------------------------------
__global__ void ovf_zero_kernel(const int* __restrict__ dst, const int* __restrict__ ovf,
                                const int* __restrict__ ovf_cnt, float* extra) {
    int m = *ovf_cnt;
    int total = m * 32;  // one float4 per thread-slot
    for (int i = blockIdx.x * blockDim.x + threadIdx.x; i < total; i += gridDim.x * blockDim.x) {
        int d = __ldg(dst + ovf[i >> 5]);
        reinterpret_cast<float4*>(extra + (size_t)d * FEAT)[i & 31] =
            make_float4(0.f, 0.f, 0.f, 0.f);
    }
}

__global__ void ovf_scatter_kernel(const int* __restrict__ src, const int* __restrict__ dst,
                                   const int* __restrict__ ovf, const int* __restrict__ ovf_cnt,
                                   const __half* __restrict__ h, float* extra) {
    int m = *ovf_cnt;
    int lane = threadIdx.x & 15;
    for (int i = blockIdx.x * 16 + (threadIdx.x >> 4); i < m; i += gridDim.x * 16) {
        int e = ovf[i];
        int s = __ldg(src + e);
        int d = __ldg(dst + e);
        const uint4 v = *(reinterpret_cast<const uint4*>(h + (size_t)s * FEAT) + lane);
        const __half2* hp = reinterpret_cast<const __half2*>(&v);
        float2 f0 = __half22float2(hp[0]), f1 = __half22float2(hp[1]);
        float2 f2 = __half22float2(hp[2]), f3 = __half22float2(hp[3]);
        float* p = extra + (size_t)d * FEAT + lane * 8;
        asm volatile("red.global.add.v4.f32 [%0], {%1, %2, %3, %4};"
                     :: "l"(p), "f"(f0.x), "f"(f0.y), "f"(f1.x), "f"(f1.y) : "memory");
        asm volatile("red.global.add.v4.f32 [%0], {%1, %2, %3, %4};"
                     :: "l"(p + 4), "f"(f2.x), "f"(f2.y), "f"(f3.x), "f"(f3.y) : "memory");
    }
}

// ---------------------------------------------------------------------------
// Gather: warp per node. result = gelu(dd * (h'[node] + sum h'[s]) + b).
// 4x edge unroll for MLP against L2-hit latency.
// ---------------------------------------------------------------------------
__device__ __forceinline__ float gelu_exact(float v) { return v * normcdff(v); }

__device__ __forceinline__ void acc_row(float4& acc, const __half* __restrict__ h,
                                        int s, int lane) {
    uint2 hv = *(reinterpret_cast<const uint2*>(h + (size_t)s * FEAT) + lane);
    float2 fa = __half22float2(*reinterpret_cast<const __half2*>(&hv.x));
    float2 fb = __half22float2(*reinterpret_cast<const __half2*>(&hv.y));
    acc.x += fa.x; acc.y += fa.y; acc.z += fb.x; acc.w += fb.y;
}

__global__ void __launch_bounds__(256)
gather_kernel(const int* __restrict__ cnt, const int* __restrict__ list,
              const float* __restrict__ dinv, const __half* __restrict__ h,
              const float* __restrict__ extra,
              const float* __restrict__ b, float* out, int n) {
    int node = blockIdx.x * 8 + (threadIdx.x >> 5);
    if (node >= n) return;
    int lane = threadIdx.x & 31;

    int m = cnt[node];
    float dd = dinv[node];

    float4 acc = make_float4(0.f, 0.f, 0.f, 0.f);
    acc_row(acc, h, node, lane);  // self loop: h'[node]

    int mb = (m > CAP) ? CAP : m;
    const int* lp = list + (size_t)node * CAP;

    for (int base = 0; base < mb; base += 32) {
        int idx = base + lane;
        int s = (idx < mb) ? lp[idx] : 0;
        int cnum = mb - base; if (cnum > 32) cnum = 32;
        int j = 0;
        for (; j + 3 < cnum; j += 4) {
            int s0 = __shfl_sync(0xFFFFFFFFu, s, j);
            int s1 = __shfl_sync(0xFFFFFFFFu, s, j + 1);
            int s2 = __shfl_sync(0xFFFFFFFFu, s, j + 2);
            int s3 = __shfl_sync(0xFFFFFFFFu, s, j + 3);
            uint2 h0 = *(reinterpret_cast<const uint2*>(h + (size_t)s0 * FEAT) + lane);
            uint2 h1 = *(reinterpret_cast<const uint2*>(h + (size_t)s1 * FEAT) + lane);
            uint2 h2 = *(reinterpret_cast<const uint2*>(h + (size_t)s2 * FEAT) + lane);
            uint2 h3 = *(reinterpret_cast<const uint2*>(h + (size_t)s3 * FEAT) + lane);
            float2 a0 = __half22float2(*reinterpret_cast<const __half2*>(&h0.x));
            float2 b0 = __half22float2(*reinterpret_cast<const __half2*>(&h0.y));
            float2 a1 = __half22float2(*reinterpret_cast<const __half2*>(&h1.x));
            float2 b1 = __half22float2(*reinterpret_cast<const __half2*>(&h1.y));
            float2 a2 = __half22float2(*reinterpret_cast<const __half2*>(&h2.x));
            float2 b2 = __half22float2(*reinterpret_cast<const __half2*>(&h2.y));
            float2 a3 = __half22float2(*reinterpret_cast<const __half2*>(&h3.x));
            float2 b3 = __half22float2(*reinterpret_cast<const __half2*>(&h3.y));
            acc.x += (a0.x + a1.x) + (a2.x + a3.x);
            acc.y += (a0.y + a1.y) + (a2.y + a3.y);
            acc.z += (b0.x + b1.x) + (b2.x + b3.x);
            acc.w += (b0.y + b1.y) + (b2.y + b3.y);
        }
        for (; j < cnum; j++) {
            int sj = __shfl_sync(0xFFFFFFFFu, s, j);
            acc_row(acc, h, sj, lane);
        }
    }

    if (m > CAP) {  // overflow contributions (not taken in practice)
        float4 ex = *(reinterpret_cast<const float4*>(extra + (size_t)node * FEAT) + lane);
        acc.x += ex.x; acc.y += ex.y; acc.z += ex.z; acc.w += ex.w;
    }

    float4 bb = *(reinterpret_cast<const float4*>(b) + lane);
    acc.x = gelu_exact(fmaf(dd, acc.x, bb.x));
    acc.y = gelu_exact(fmaf(dd, acc.y, bb.y));
    acc.z = gelu_exact(fmaf(dd, acc.z, bb.z));
    acc.w = gelu_exact(fmaf(dd, acc.w, bb.w));
    *(reinterpret_cast<float4*>(out + (size_t)node * FEAT) + lane) = acc;
}

// ---------------------------------------------------------------------------
// Launch
// ---------------------------------------------------------------------------
extern "C" void kernel_launch(void* const* d_in, const int* in_sizes, int n_in,
                              void* d_out, int out_size) {
    const float* x  = (const float*)d_in[0];
    const int*   ei = (const int*)d_in[1];
    const float* W  = (const float*)d_in[2];
    const float* b  = (const float*)d_in[3];
    float* out = (float*)d_out;

    int n = in_sizes[0] / FEAT;
    int E = in_sizes[1] / 2;
    const int* src = ei;
    const int* dst = ei + E;

    __half *h_ptr, *wh_ptr; float *dinv_ptr, *extra_ptr;
    int *cnt_ptr, *list_ptr, *ovf_ptr, *ovfc_ptr;
    cudaGetSymbolAddress((void**)&h_ptr, g_h);
    cudaGetSymbolAddress((void**)&wh_ptr, g_wh);
    cudaGetSymbolAddress((void**)&dinv_ptr, g_dinv);
    cudaGetSymbolAddress((void**)&cnt_ptr, g_cnt);
    cudaGetSymbolAddress((void**)&list_ptr, g_list);
    cudaGetSymbolAddress((void**)&ovf_ptr, g_ovf);
    cudaGetSymbolAddress((void**)&ovfc_ptr, g_ovf_cnt);
    cudaGetSymbolAddress((void**)&extra_ptr, g_extra);

    zero_kernel<<<(n + 255) / 256, 256>>>(cnt_ptr, ovfc_ptr, n);
    wconv_kernel<<<(FEAT * FEAT / 4 + 255) / 256, 256>>>(W, wh_ptr);
    fill_kernel<<<(E + 255) / 256, 256>>>(src, dst, cnt_ptr, list_ptr, ovf_ptr, ovfc_ptr, E);
    dinv_kernel<<<(n + 255) / 256, 256>>>(cnt_ptr, dinv_ptr, n);

    int smem_bytes = (FEAT + BM) * WPADH * (int)sizeof(__half);  // ~68 KB
    cudaFuncSetAttribute(gemm_kernel, cudaFuncAttributeMaxDynamicSharedMemorySize, smem_bytes);
    gemm_kernel<<<(n + BM - 1) / BM, 512, smem_bytes>>>(x, wh_ptr, dinv_ptr, h_ptr, n);

    ovf_zero_kernel<<<32, 256>>>(dst, ovf_ptr, ovfc_ptr, extra_ptr);
    ovf_scatter_kernel<<<32, 256>>>(src, dst, ovf_ptr, ovfc_ptr, h_ptr, extra_ptr);

    gather_kernel<<<(n + 7) / 8, 256>>>(cnt_ptr, list_ptr, dinv_ptr, h_ptr,
                                        extra_ptr, b, out, n);
}

// round 7
// speedup vs baseline: 3.6851x; 1.0963x over previous
#include <cuda_runtime.h>
#include <cuda_fp16.h>
#include <cstdint>

#define N_NODES_MAX 50000
#define N_EDGES_MAX 800000
#define FEAT 128
#define BM 128
#define WPADH 136  // padded half row: 272 B = 17*16B -> conflict-free ldmatrix
#define CAP 64     // per-node bucket capacity (deg ~Poisson(16); overflow handled inline)

// Scratch (allocation-free rule: __device__ globals)
__device__ __half g_h[N_NODES_MAX * FEAT];      // h' = (x@W) * dinv[row], fp16
__device__ __half g_wh[FEAT * FEAT];            // fp16 W (converted once per launch)
__device__ int    g_cnt[N_NODES_MAX];
__device__ int    g_list[N_NODES_MAX * CAP];    // bucketed src indices
__device__ int    g_ovf[N_EDGES_MAX];           // overflow edge ids (unused in practice)
__device__ int    g_ovf_cnt;

// ---------------------------------------------------------------------------
// Prep: zero counters + convert W to fp16 (one launch)
// ---------------------------------------------------------------------------
__global__ void prep_kernel(const float* __restrict__ W, __half* __restrict__ wh,
                            int* cnt, int* ovf_cnt, int n) {
    int i = blockIdx.x * blockDim.x + threadIdx.x;
    if (i < n) cnt[i] = 0;
    if (i == 0) *ovf_cnt = 0;
    if (i < FEAT * FEAT / 4) {
        float4 v = reinterpret_cast<const float4*>(W)[i];
        __half2* d = reinterpret_cast<__half2*>(wh + i * 4);
        d[0] = __floats2half2_rn(v.x, v.y);
        d[1] = __floats2half2_rn(v.z, v.w);
    }
}

// ---------------------------------------------------------------------------
// Fill buckets: histogram + bin in one pass
// ---------------------------------------------------------------------------
__global__ void fill_kernel(const int* __restrict__ src, const int* __restrict__ dst,
                            int* cnt, int* list, int* ovf, int* ovf_cnt, int E) {
    int e = blockIdx.x * blockDim.x + threadIdx.x;
    if (e >= E) return;
    int d = __ldg(dst + e);
    int p = atomicAdd(&cnt[d], 1);
    if (p < CAP) list[d * CAP + p] = __ldg(src + e);
    else         ovf[atomicAdd(ovf_cnt, 1)] = e;
}

// ---------------------------------------------------------------------------
// Tensor-core helpers
// ---------------------------------------------------------------------------
__device__ __forceinline__ uint32_t smem_u32(const void* p) {
    return (uint32_t)__cvta_generic_to_shared(p);
}
__device__ __forceinline__ void ldmatrix_x4(uint32_t& r0, uint32_t& r1,
                                            uint32_t& r2, uint32_t& r3, uint32_t addr) {
    asm volatile("ldmatrix.sync.aligned.m8n8.x4.shared.b16 {%0,%1,%2,%3}, [%4];"
                 : "=r"(r0), "=r"(r1), "=r"(r2), "=r"(r3) : "r"(addr));
}
__device__ __forceinline__ void ldmatrix_x2_trans(uint32_t& r0, uint32_t& r1, uint32_t addr) {
    asm volatile("ldmatrix.sync.aligned.m8n8.x2.trans.shared.b16 {%0,%1}, [%2];"
                 : "=r"(r0), "=r"(r1) : "r"(addr));
}
__device__ __forceinline__ void mma16816(float* c, uint32_t a0, uint32_t a1,
                                         uint32_t a2, uint32_t a3,
                                         uint32_t b0, uint32_t b1) {
    asm volatile(
        "mma.sync.aligned.m16n8k16.row.col.f32.f16.f16.f32 "
        "{%0,%1,%2,%3}, {%4,%5,%6,%7}, {%8,%9}, {%0,%1,%2,%3};"
        : "+f"(c[0]), "+f"(c[1]), "+f"(c[2]), "+f"(c[3])
        : "r"(a0), "r"(a1), "r"(a2), "r"(a3), "r"(b0), "r"(b1));
}

// ---------------------------------------------------------------------------
// GEMM: h' = (x @ W) * rsqrt(cnt[row]+1), fp16 out. Tile 128x128, 512 threads.
// ---------------------------------------------------------------------------
__global__ void __launch_bounds__(512)
gemm_kernel(const float* __restrict__ x, const __half* __restrict__ wh,
            const int* __restrict__ cnt, __half* __restrict__ h, int n) {
    extern __shared__ __half sh[];
    __half* Wh = sh;                    // [128][WPADH]
    __half* Xh = sh + FEAT * WPADH;     // [BM][WPADH]

    int tid = threadIdx.x;
    int r0blk = blockIdx.x * BM;

    // Stage W (already fp16): 2048 uint4
    {
        const uint4* w4 = reinterpret_cast<const uint4*>(wh);
#pragma unroll
        for (int i = 0; i < 4; i++) {
            int idx = i * 512 + tid;
            int r = idx >> 4, c = idx & 15;
            *reinterpret_cast<uint4*>(Wh + r * WPADH + c * 8) = w4[idx];
        }
    }
    // Stage X tile (fp32 -> fp16): 128x32 float4 = 4096
    {
        const float4* x4 = reinterpret_cast<const float4*>(x);
#pragma unroll
        for (int i = 0; i < 8; i++) {
            int idx = i * 512 + tid;
            int r = idx >> 5, c4 = idx & 31;
            int row = r0blk + r;
            float4 v = make_float4(0.f, 0.f, 0.f, 0.f);
            if (row < n) v = x4[(size_t)row * 32 + c4];
            __half2* d = reinterpret_cast<__half2*>(Xh + r * WPADH + c4 * 4);
            d[0] = __floats2half2_rn(v.x, v.y);
            d[1] = __floats2half2_rn(v.z, v.w);
        }
    }
    __syncthreads();

    int w = tid >> 5, lane = tid & 31;
    int wr = w & 7;        // 8 row groups of 16
    int wc = w >> 3;       // 2 col groups of 64

    float acc[8][4];
#pragma unroll
    for (int nt = 0; nt < 8; nt++)
#pragma unroll
        for (int j = 0; j < 4; j++) acc[nt][j] = 0.f;

    int t = lane >> 3, r8 = lane & 7;
    int a_row = wr * 16 + (t & 1) * 8 + r8;
    int a_kof = (t >> 1) * 8;
    uint32_t a_base = smem_u32(Xh + a_row * WPADH + a_kof);
    int bt = (lane >> 3) & 1;
    uint32_t b_base = smem_u32(Wh + (bt * 8 + r8) * WPADH + wc * 64);

#pragma unroll
    for (int kk = 0; kk < 8; kk++) {
        uint32_t a0, a1, a2, a3;
        ldmatrix_x4(a0, a1, a2, a3, a_base + kk * 16 * sizeof(__half));
        uint32_t brow = b_base + kk * 16 * WPADH * sizeof(__half);
#pragma unroll
        for (int nt = 0; nt < 8; nt++) {
            uint32_t b0, b1;
            ldmatrix_x2_trans(b0, b1, brow + nt * 8 * sizeof(__half));
            mma16816(acc[nt], a0, a1, a2, a3, b0, b1);
        }
    }

    int group = lane >> 2, tg = lane & 3;
    int r_lo = r0blk + wr * 16 + group;
    int r_hi = r_lo + 8;
    float di_lo = (r_lo < n) ? rsqrtf((float)(__ldg(cnt + r_lo) + 1)) : 0.f;
    float di_hi = (r_hi < n) ? rsqrtf((float)(__ldg(cnt + r_hi) + 1)) : 0.f;

#pragma unroll
    for (int nt = 0; nt < 8; nt++) {
        int col = wc * 64 + nt * 8 + tg * 2;
        if (r_lo < n)
            *reinterpret_cast<__half2*>(h + (size_t)r_lo * FEAT + col) =
                __floats2half2_rn(acc[nt][0] * di_lo, acc[nt][1] * di_lo);
        if (r_hi < n)
            *reinterpret_cast<__half2*>(h + (size_t)r_hi * FEAT + col) =
                __floats2half2_rn(acc[nt][2] * di_hi, acc[nt][3] * di_hi);
    }
}

// ---------------------------------------------------------------------------
// Gather: warp per node. result = gelu(dd * (h'[node] + sum h'[s]) + b).
// 8x edge unroll for MLP against L2-hit latency. Overflow handled inline by
// scanning g_ovf (empty in practice).
// ---------------------------------------------------------------------------
__device__ __forceinline__ float gelu_exact(float v) { return v * normcdff(v); }

__device__ __forceinline__ void acc_row(float4& acc, const __half* __restrict__ h,
                                        int s, int lane) {
    uint2 hv = *(reinterpret_cast<const uint2*>(h + (size_t)s * FEAT) + lane);
    float2 fa = __half22float2(*reinterpret_cast<const __half2*>(&hv.x));
    float2 fb = __half22float2(*reinterpret_cast<const __half2*>(&hv.y));
    acc.x += fa.x; acc.y += fa.y; acc.z += fb.x; acc.w += fb.y;
}

__global__ void __launch_bounds__(256)
gather_kernel(const int* __restrict__ cnt, const int* __restrict__ list,
              const __half* __restrict__ h,
              const int* __restrict__ src, const int* __restrict__ dst,
              const int* __restrict__ ovf, const int* __restrict__ ovf_cnt,
              const float* __restrict__ b, float* out, int n) {
    int node = blockIdx.x * 8 + (threadIdx.x >> 5);
    if (node >= n) return;
    int lane = threadIdx.x & 31;

    int m = cnt[node];
    float dd = rsqrtf((float)(m + 1));

    float4 acc = make_float4(0.f, 0.f, 0.f, 0.f);
    acc_row(acc, h, node, lane);  // self loop: h'[node]

    int mb = (m > CAP) ? CAP : m;
    const int* lp = list + (size_t)node * CAP;

    for (int base = 0; base < mb; base += 32) {
        int idx = base + lane;
        int s = (idx < mb) ? lp[idx] : 0;
        int cnum = mb - base; if (cnum > 32) cnum = 32;
        int j = 0;
        for (; j + 7 < cnum; j += 8) {
            uint2 hv[8];
#pragma unroll
            for (int q = 0; q < 8; q++) {
                int sq = __shfl_sync(0xFFFFFFFFu, s, j + q);
                hv[q] = *(reinterpret_cast<const uint2*>(h + (size_t)sq * FEAT) + lane);
            }
#pragma unroll
            for (int q = 0; q < 8; q++) {
                float2 fa = __half22float2(*reinterpret_cast<const __half2*>(&hv[q].x));
                float2 fb = __half22float2(*reinterpret_cast<const __half2*>(&hv[q].y));
                acc.x += fa.x; acc.y += fa.y; acc.z += fb.x; acc.w += fb.y;
            }
        }
        for (; j < cnum; j++) {
            int sj = __shfl_sync(0xFFFFFFFFu, s, j);
            acc_row(acc, h, sj, lane);
        }
    }

    if (m > CAP) {  // inline overflow scan (ovf list empty in practice)
        int movf = *ovf_cnt;
        for (int i = 0; i < movf; i++) {
            int e = __ldg(ovf + i);
            if (__ldg(dst + e) == node) acc_row(acc, h, __ldg(src + e), lane);
        }
    }

    float4 bb = *(reinterpret_cast<const float4*>(b) + lane);
    acc.x = gelu_exact(fmaf(dd, acc.x, bb.x));
    acc.y = gelu_exact(fmaf(dd, acc.y, bb.y));
    acc.z = gelu_exact(fmaf(dd, acc.z, bb.z));
    acc.w = gelu_exact(fmaf(dd, acc.w, bb.w));
    *(reinterpret_cast<float4*>(out + (size_t)node * FEAT) + lane) = acc;
}

// ---------------------------------------------------------------------------
// Launch: 4 kernels total (prep -> fill -> gemm -> gather)
// ---------------------------------------------------------------------------
extern "C" void kernel_launch(void* const* d_in, const int* in_sizes, int n_in,
                              void* d_out, int out_size) {
    const float* x  = (const float*)d_in[0];
    const int*   ei = (const int*)d_in[1];
    const float* W  = (const float*)d_in[2];
    const float* b  = (const float*)d_in[3];
    float* out = (float*)d_out;

    int n = in_sizes[0] / FEAT;
    int E = in_sizes[1] / 2;
    const int* src = ei;
    const int* dst = ei + E;

    __half *h_ptr, *wh_ptr;
    int *cnt_ptr, *list_ptr, *ovf_ptr, *ovfc_ptr;
    cudaGetSymbolAddress((void**)&h_ptr, g_h);
    cudaGetSymbolAddress((void**)&wh_ptr, g_wh);
    cudaGetSymbolAddress((void**)&cnt_ptr, g_cnt);
    cudaGetSymbolAddress((void**)&list_ptr, g_list);
    cudaGetSymbolAddress((void**)&ovf_ptr, g_ovf);
    cudaGetSymbolAddress((void**)&ovfc_ptr, g_ovf_cnt);

    int prep_threads = (n > FEAT * FEAT / 4) ? n : FEAT * FEAT / 4;
    prep_kernel<<<(prep_threads + 255) / 256, 256>>>(W, wh_ptr, cnt_ptr, ovfc_ptr, n);

    fill_kernel<<<(E + 255) / 256, 256>>>(src, dst, cnt_ptr, list_ptr, ovf_ptr, ovfc_ptr, E);

    int smem_bytes = (FEAT + BM) * WPADH * (int)sizeof(__half);  // ~68 KB
    cudaFuncSetAttribute(gemm_kernel, cudaFuncAttributeMaxDynamicSharedMemorySize, smem_bytes);
    gemm_kernel<<<(n + BM - 1) / BM, 512, smem_bytes>>>(x, wh_ptr, cnt_ptr, h_ptr, n);

    gather_kernel<<<(n + 7) / 8, 256>>>(cnt_ptr, list_ptr, h_ptr,
                                        src, dst, ovf_ptr, ovfc_ptr, b, out, n);
}

// round 9
// speedup vs baseline: 3.6925x; 1.0020x over previous
#include <cuda_runtime.h>
#include <cuda_fp16.h>
#include <cstdint>

#define N_NODES_MAX 50000
#define N_EDGES_MAX 800000
#define FEAT 128
#define BM 128
#define WPADH 136  // padded half row: 272 B = 17*16B -> conflict-free ldmatrix
#define CAP 64     // per-node bucket capacity (deg ~Poisson(16); overflow handled inline)

// Scratch (allocation-free rule: __device__ globals)
__device__ __half g_h[N_NODES_MAX * FEAT];      // h' = (x@W) * dinv[row], fp16
__device__ __half g_wh[FEAT * FEAT];            // fp16 W (converted once per launch)
__device__ int    g_cnt[N_NODES_MAX];
__device__ int    g_list[N_NODES_MAX * CAP];    // bucketed src indices
__device__ int    g_ovf[N_EDGES_MAX];           // overflow edge ids (unused in practice)
__device__ int    g_ovf_cnt;

// ---------------------------------------------------------------------------
// Prep: zero counters + convert W to fp16 (one launch)
// ---------------------------------------------------------------------------
__global__ void prep_kernel(const float* __restrict__ W, __half* __restrict__ wh,
                            int* cnt, int* ovf_cnt, int n) {
    int i = blockIdx.x * blockDim.x + threadIdx.x;
    if (i < n) cnt[i] = 0;
    if (i == 0) *ovf_cnt = 0;
    if (i < FEAT * FEAT / 4) {
        float4 v = reinterpret_cast<const float4*>(W)[i];
        __half2* d = reinterpret_cast<__half2*>(wh + i * 4);
        d[0] = __floats2half2_rn(v.x, v.y);
        d[1] = __floats2half2_rn(v.z, v.w);
    }
}

// ---------------------------------------------------------------------------
// Fill buckets: histogram + bin in one pass
// ---------------------------------------------------------------------------
__global__ void fill_kernel(const int* __restrict__ src, const int* __restrict__ dst,
                            int* cnt, int* list, int* ovf, int* ovf_cnt, int E) {
    int e = blockIdx.x * blockDim.x + threadIdx.x;
    if (e >= E) return;
    int d = __ldg(dst + e);
    int p = atomicAdd(&cnt[d], 1);
    if (p < CAP) list[d * CAP + p] = __ldg(src + e);
    else         ovf[atomicAdd(ovf_cnt, 1)] = e;
}

// ---------------------------------------------------------------------------
// Tensor-core helpers
// ---------------------------------------------------------------------------
__device__ __forceinline__ uint32_t smem_u32(const void* p) {
    return (uint32_t)__cvta_generic_to_shared(p);
}
__device__ __forceinline__ void ldmatrix_x4(uint32_t& r0, uint32_t& r1,
                                            uint32_t& r2, uint32_t& r3, uint32_t addr) {
    asm volatile("ldmatrix.sync.aligned.m8n8.x4.shared.b16 {%0,%1,%2,%3}, [%4];"
                 : "=r"(r0), "=r"(r1), "=r"(r2), "=r"(r3) : "r"(addr));
}
__device__ __forceinline__ void ldmatrix_x2_trans(uint32_t& r0, uint32_t& r1, uint32_t addr) {
    asm volatile("ldmatrix.sync.aligned.m8n8.x2.trans.shared.b16 {%0,%1}, [%2];"
                 : "=r"(r0), "=r"(r1) : "r"(addr));
}
__device__ __forceinline__ void mma16816(float* c, uint32_t a0, uint32_t a1,
                                         uint32_t a2, uint32_t a3,
                                         uint32_t b0, uint32_t b1) {
    asm volatile(
        "mma.sync.aligned.m16n8k16.row.col.f32.f16.f16.f32 "
        "{%0,%1,%2,%3}, {%4,%5,%6,%7}, {%8,%9}, {%0,%1,%2,%3};"
        : "+f"(c[0]), "+f"(c[1]), "+f"(c[2]), "+f"(c[3])
        : "r"(a0), "r"(a1), "r"(a2), "r"(a3), "r"(b0), "r"(b1));
}

// ---------------------------------------------------------------------------
// GEMM: h' = (x @ W) * rsqrt(cnt[row]+1), fp16 out. Tile 128x128, 512 threads.
// ---------------------------------------------------------------------------
__global__ void __launch_bounds__(512)
gemm_kernel(const float* __restrict__ x, const __half* __restrict__ wh,
            const int* __restrict__ cnt, __half* __restrict__ h, int n) {
    extern __shared__ __half sh[];
    __half* Wh = sh;                    // [128][WPADH]
    __half* Xh = sh + FEAT * WPADH;     // [BM][WPADH]

    int tid = threadIdx.x;
    int r0blk = blockIdx.x * BM;

    // Stage W (already fp16): 2048 uint4
    {
        const uint4* w4 = reinterpret_cast<const uint4*>(wh);
#pragma unroll
        for (int i = 0; i < 4; i++) {
            int idx = i * 512 + tid;
            int r = idx >> 4, c = idx & 15;
            *reinterpret_cast<uint4*>(Wh + r * WPADH + c * 8) = w4[idx];
        }
    }
    // Stage X tile (fp32 -> fp16): 128x32 float4 = 4096
    {
        const float4* x4 = reinterpret_cast<const float4*>(x);
#pragma unroll
        for (int i = 0; i < 8; i++) {
            int idx = i * 512 + tid;
            int r = idx >> 5, c4 = idx & 31;
            int row = r0blk + r;
            float4 v = make_float4(0.f, 0.f, 0.f, 0.f);
            if (row < n) v = x4[(size_t)row * 32 + c4];
            __half2* d = reinterpret_cast<__half2*>(Xh + r * WPADH + c4 * 4);
            d[0] = __floats2half2_rn(v.x, v.y);
            d[1] = __floats2half2_rn(v.z, v.w);
        }
    }
    __syncthreads();

    int w = tid >> 5, lane = tid & 31;
    int wr = w & 7;        // 8 row groups of 16
    int wc = w >> 3;       // 2 col groups of 64

    float acc[8][4];
#pragma unroll
    for (int nt = 0; nt < 8; nt++)
#pragma unroll
        for (int j = 0; j < 4; j++) acc[nt][j] = 0.f;

    int t = lane >> 3, r8 = lane & 7;
    int a_row = wr * 16 + (t & 1) * 8 + r8;
    int a_kof = (t >> 1) * 8;
    uint32_t a_base = smem_u32(Xh + a_row * WPADH + a_kof);
    int bt = (lane >> 3) & 1;
    uint32_t b_base = smem_u32(Wh + (bt * 8 + r8) * WPADH + wc * 64);

#pragma unroll
    for (int kk = 0; kk < 8; kk++) {
        uint32_t a0, a1, a2, a3;
        ldmatrix_x4(a0, a1, a2, a3, a_base + kk * 16 * sizeof(__half));
        uint32_t brow = b_base + kk * 16 * WPADH * sizeof(__half);
#pragma unroll
        for (int nt = 0; nt < 8; nt++) {
            uint32_t b0, b1;
            ldmatrix_x2_trans(b0, b1, brow + nt * 8 * sizeof(__half));
            mma16816(acc[nt], a0, a1, a2, a3, b0, b1);
        }
    }

    int group = lane >> 2, tg = lane & 3;
    int r_lo = r0blk + wr * 16 + group;
    int r_hi = r_lo + 8;
    float di_lo = (r_lo < n) ? rsqrtf((float)(__ldg(cnt + r_lo) + 1)) : 0.f;
    float di_hi = (r_hi < n) ? rsqrtf((float)(__ldg(cnt + r_hi) + 1)) : 0.f;

#pragma unroll
    for (int nt = 0; nt < 8; nt++) {
        int col = wc * 64 + nt * 8 + tg * 2;
        if (r_lo < n)
            *reinterpret_cast<__half2*>(h + (size_t)r_lo * FEAT + col) =
                __floats2half2_rn(acc[nt][0] * di_lo, acc[nt][1] * di_lo);
        if (r_hi < n)
            *reinterpret_cast<__half2*>(h + (size_t)r_hi * FEAT + col) =
                __floats2half2_rn(acc[nt][2] * di_hi, acc[nt][3] * di_hi);
    }
}

// ---------------------------------------------------------------------------
// Gather: warp per node. result = gelu(dd * (h'[node] + sum h'[s]) + b).
// Inner loop: 8-edge unroll; each quad of edges summed with a 2-level fp16
// HADD2 tree (max 2 roundings/term), then converted once and added to the
// fp32 accumulator. Tail + self-loop use the exact fp32 path.
// ---------------------------------------------------------------------------
__device__ __forceinline__ float gelu_exact(float v) { return v * normcdff(v); }

__device__ __forceinline__ void acc_row(float4& acc, const uint2* __restrict__ hb, int s) {
    uint2 hv = hb[s * 32];
    float2 fa = __half22float2(*reinterpret_cast<const __half2*>(&hv.x));
    float2 fb = __half22float2(*reinterpret_cast<const __half2*>(&hv.y));
    acc.x += fa.x; acc.y += fa.y; acc.z += fb.x; acc.w += fb.y;
}

__device__ __forceinline__ void acc_quad(float4& acc, const uint2 hv[4]) {
    const __half2* p0 = reinterpret_cast<const __half2*>(&hv[0]);
    const __half2* p1 = reinterpret_cast<const __half2*>(&hv[1]);
    const __half2* p2 = reinterpret_cast<const __half2*>(&hv[2]);
    const __half2* p3 = reinterpret_cast<const __half2*>(&hv[3]);
    __half2 xs = __hadd2(__hadd2(p0[0], p1[0]), __hadd2(p2[0], p3[0]));
    __half2 ys = __hadd2(__hadd2(p0[1], p1[1]), __hadd2(p2[1], p3[1]));
    float2 fx = __half22float2(xs);
    float2 fy = __half22float2(ys);
    acc.x += fx.x; acc.y += fx.y; acc.z += fy.x; acc.w += fy.y;
}

__global__ void __launch_bounds__(256)
gather_kernel(const int* __restrict__ cnt, const int* __restrict__ list,
              const __half* __restrict__ h,
              const int* __restrict__ src, const int* __restrict__ dst,
              const int* __restrict__ ovf, const int* __restrict__ ovf_cnt,
              const float* __restrict__ b, float* out, int n) {
    int node = blockIdx.x * 8 + (threadIdx.x >> 5);
    if (node >= n) return;
    int lane = threadIdx.x & 31;

    int m = cnt[node];
    float dd = rsqrtf((float)(m + 1));

    const uint2* hb = reinterpret_cast<const uint2*>(h) + lane;  // row stride = 32 uint2

    float4 acc = make_float4(0.f, 0.f, 0.f, 0.f);
    acc_row(acc, hb, node);  // self loop: h'[node], exact fp32 path

    int mb = (m > CAP) ? CAP : m;
    const int* lp = list + (size_t)node * CAP;

    for (int base = 0; base < mb; base += 32) {
        int idx = base + lane;
        int s = (idx < mb) ? lp[idx] : 0;
        int cnum = mb - base; if (cnum > 32) cnum = 32;
        int j = 0;
        for (; j + 7 < cnum; j += 8) {
            uint2 hv[8];
#pragma unroll
            for (int q = 0; q < 8; q++) {
                int sq = __shfl_sync(0xFFFFFFFFu, s, j + q);
                hv[q] = hb[sq * 32];
            }
            acc_quad(acc, hv);
            acc_quad(acc, hv + 4);
        }
        for (; j < cnum; j++) {
            int sj = __shfl_sync(0xFFFFFFFFu, s, j);
            acc_row(acc, hb, sj);  // exact fp32 tail
        }
    }

    if (m > CAP) {  // inline overflow scan (ovf list empty in practice)
        int movf = *ovf_cnt;
        for (int i = 0; i < movf; i++) {
            int e = __ldg(ovf + i);
            if (__ldg(dst + e) == node) acc_row(acc, hb, __ldg(src + e));
        }
    }

    float4 bb = *(reinterpret_cast<const float4*>(b) + lane);
    acc.x = gelu_exact(fmaf(dd, acc.x, bb.x));
    acc.y = gelu_exact(fmaf(dd, acc.y, bb.y));
    acc.z = gelu_exact(fmaf(dd, acc.z, bb.z));
    acc.w = gelu_exact(fmaf(dd, acc.w, bb.w));
    *(reinterpret_cast<float4*>(out + (size_t)node * FEAT) + lane) = acc;
}

// ---------------------------------------------------------------------------
// Launch: 4 kernels total (prep -> fill -> gemm -> gather)
// ---------------------------------------------------------------------------
extern "C" void kernel_launch(void* const* d_in, const int* in_sizes, int n_in,
                              void* d_out, int out_size) {
    const float* x  = (const float*)d_in[0];
    const int*   ei = (const int*)d_in[1];
    const float* W  = (const float*)d_in[2];
    const float* b  = (const float*)d_in[3];
    float* out = (float*)d_out;

    int n = in_sizes[0] / FEAT;
    int E = in_sizes[1] / 2;
    const int* src = ei;
    const int* dst = ei + E;

    __half *h_ptr, *wh_ptr;
    int *cnt_ptr, *list_ptr, *ovf_ptr, *ovfc_ptr;
    cudaGetSymbolAddress((void**)&h_ptr, g_h);
    cudaGetSymbolAddress((void**)&wh_ptr, g_wh);
    cudaGetSymbolAddress((void**)&cnt_ptr, g_cnt);
    cudaGetSymbolAddress((void**)&list_ptr, g_list);
    cudaGetSymbolAddress((void**)&ovf_ptr, g_ovf);
    cudaGetSymbolAddress((void**)&ovfc_ptr, g_ovf_cnt);

    int prep_threads = (n > FEAT * FEAT / 4) ? n : FEAT * FEAT / 4;
    prep_kernel<<<(prep_threads + 255) / 256, 256>>>(W, wh_ptr, cnt_ptr, ovfc_ptr, n);

    fill_kernel<<<(E + 255) / 256, 256>>>(src, dst, cnt_ptr, list_ptr, ovf_ptr, ovfc_ptr, E);

    int smem_bytes = (FEAT + BM) * WPADH * (int)sizeof(__half);  // ~68 KB
    cudaFuncSetAttribute(gemm_kernel, cudaFuncAttributeMaxDynamicSharedMemorySize, smem_bytes);
    gemm_kernel<<<(n + BM - 1) / BM, 512, smem_bytes>>>(x, wh_ptr, cnt_ptr, h_ptr, n);

    gather_kernel<<<(n + 7) / 8, 256>>>(cnt_ptr, list_ptr, h_ptr,
                                        src, dst, ovf_ptr, ovfc_ptr, b, out, n);
}

// round 10
// speedup vs baseline: 4.3906x; 1.1891x over previous
#include <cuda_runtime.h>
#include <cuda_fp16.h>
#include <cstdint>

#define N_NODES_MAX 50000
#define N_EDGES_MAX 800000
#define FEAT 128
#define BM 128
#define WPADH 136  // padded half row: 272 B = 17*16B -> conflict-free ldmatrix
#define CAP 64     // per-node bucket capacity (deg ~Poisson(16); overflow handled inline)

// Scratch (allocation-free rule: __device__ globals)
__device__ __half g_h[N_NODES_MAX * FEAT];      // h' = (x@W) * dinv[row], fp16
__device__ __half g_wh[FEAT * FEAT];            // fp16 W (converted once per launch)
__device__ int    g_cnt[N_NODES_MAX];           // zero at load; re-zeroed by gather each run
__device__ int    g_list[N_NODES_MAX * CAP];    // bucketed src indices
__device__ int    g_ovf[N_EDGES_MAX];           // overflow edge ids (unused in practice)
__device__ int    g_ovf_cnt;

// ---------------------------------------------------------------------------
// Prep: convert W to fp16 + reset overflow counter (cnt zeroing lives in
// gather's epilogue -> invariant: cnt==0 at every kernel_launch entry)
// ---------------------------------------------------------------------------
__global__ void prep_kernel(const float* __restrict__ W, __half* __restrict__ wh,
                            int* ovf_cnt) {
    int i = blockIdx.x * blockDim.x + threadIdx.x;
    if (i == 0) *ovf_cnt = 0;
    if (i < FEAT * FEAT / 4) {
        float4 v = reinterpret_cast<const float4*>(W)[i];
        __half2* d = reinterpret_cast<__half2*>(wh + i * 4);
        d[0] = __floats2half2_rn(v.x, v.y);
        d[1] = __floats2half2_rn(v.z, v.w);
    }
}

// ---------------------------------------------------------------------------
// Fill buckets: histogram + bin in one pass
// ---------------------------------------------------------------------------
__global__ void fill_kernel(const int* __restrict__ src, const int* __restrict__ dst,
                            int* cnt, int* list, int* ovf, int* ovf_cnt, int E) {
    int e = blockIdx.x * blockDim.x + threadIdx.x;
    if (e >= E) return;
    int d = __ldg(dst + e);
    int p = atomicAdd(&cnt[d], 1);
    if (p < CAP) list[d * CAP + p] = __ldg(src + e);
    else         ovf[atomicAdd(ovf_cnt, 1)] = e;
}

// ---------------------------------------------------------------------------
// Tensor-core helpers
// ---------------------------------------------------------------------------
__device__ __forceinline__ uint32_t smem_u32(const void* p) {
    return (uint32_t)__cvta_generic_to_shared(p);
}
__device__ __forceinline__ void ldmatrix_x4(uint32_t& r0, uint32_t& r1,
                                            uint32_t& r2, uint32_t& r3, uint32_t addr) {
    asm volatile("ldmatrix.sync.aligned.m8n8.x4.shared.b16 {%0,%1,%2,%3}, [%4];"
                 : "=r"(r0), "=r"(r1), "=r"(r2), "=r"(r3) : "r"(addr));
}
__device__ __forceinline__ void ldmatrix_x2_trans(uint32_t& r0, uint32_t& r1, uint32_t addr) {
    asm volatile("ldmatrix.sync.aligned.m8n8.x2.trans.shared.b16 {%0,%1}, [%2];"
                 : "=r"(r0), "=r"(r1) : "r"(addr));
}
__device__ __forceinline__ void mma16816(float* c, uint32_t a0, uint32_t a1,
                                         uint32_t a2, uint32_t a3,
                                         uint32_t b0, uint32_t b1) {
    asm volatile(
        "mma.sync.aligned.m16n8k16.row.col.f32.f16.f16.f32 "
        "{%0,%1,%2,%3}, {%4,%5,%6,%7}, {%8,%9}, {%0,%1,%2,%3};"
        : "+f"(c[0]), "+f"(c[1]), "+f"(c[2]), "+f"(c[3])
        : "r"(a0), "r"(a1), "r"(a2), "r"(a3), "r"(b0), "r"(b1));
}

// ---------------------------------------------------------------------------
// GEMM: h' = (x @ W) * rsqrt(cnt[row]+1), fp16 out. Tile 128x128, 512 threads.
// ---------------------------------------------------------------------------
__global__ void __launch_bounds__(512)
gemm_kernel(const float* __restrict__ x, const __half* __restrict__ wh,
            const int* __restrict__ cnt, __half* __restrict__ h, int n) {
    extern __shared__ __half sh[];
    __half* Wh = sh;                    // [128][WPADH]
    __half* Xh = sh + FEAT * WPADH;     // [BM][WPADH]

    int tid = threadIdx.x;
    int r0blk = blockIdx.x * BM;

    // Stage W (already fp16): 2048 uint4
    {
        const uint4* w4 = reinterpret_cast<const uint4*>(wh);
#pragma unroll
        for (int i = 0; i < 4; i++) {
            int idx = i * 512 + tid;
            int r = idx >> 4, c = idx & 15;
            *reinterpret_cast<uint4*>(Wh + r * WPADH + c * 8) = w4[idx];
        }
    }
    // Stage X tile (fp32 -> fp16): 128x32 float4 = 4096
    {
        const float4* x4 = reinterpret_cast<const float4*>(x);
#pragma unroll
        for (int i = 0; i < 8; i++) {
            int idx = i * 512 + tid;
            int r = idx >> 5, c4 = idx & 31;
            int row = r0blk + r;
            float4 v = make_float4(0.f, 0.f, 0.f, 0.f);
            if (row < n) v = x4[(size_t)row * 32 + c4];
            __half2* d = reinterpret_cast<__half2*>(Xh + r * WPADH + c4 * 4);
            d[0] = __floats2half2_rn(v.x, v.y);
            d[1] = __floats2half2_rn(v.z, v.w);
        }
    }
    __syncthreads();

    int w = tid >> 5, lane = tid & 31;
    int wr = w & 7;        // 8 row groups of 16
    int wc = w >> 3;       // 2 col groups of 64

    float acc[8][4];
#pragma unroll
    for (int nt = 0; nt < 8; nt++)
#pragma unroll
        for (int j = 0; j < 4; j++) acc[nt][j] = 0.f;

    int t = lane >> 3, r8 = lane & 7;
    int a_row = wr * 16 + (t & 1) * 8 + r8;
    int a_kof = (t >> 1) * 8;
    uint32_t a_base = smem_u32(Xh + a_row * WPADH + a_kof);
    int bt = (lane >> 3) & 1;
    uint32_t b_base = smem_u32(Wh + (bt * 8 + r8) * WPADH + wc * 64);

#pragma unroll
    for (int kk = 0; kk < 8; kk++) {
        uint32_t a0, a1, a2, a3;
        ldmatrix_x4(a0, a1, a2, a3, a_base + kk * 16 * sizeof(__half));
        uint32_t brow = b_base + kk * 16 * WPADH * sizeof(__half);
#pragma unroll
        for (int nt = 0; nt < 8; nt++) {
            uint32_t b0, b1;
            ldmatrix_x2_trans(b0, b1, brow + nt * 8 * sizeof(__half));
            mma16816(acc[nt], a0, a1, a2, a3, b0, b1);
        }
    }

    int group = lane >> 2, tg = lane & 3;
    int r_lo = r0blk + wr * 16 + group;
    int r_hi = r_lo + 8;
    float di_lo = (r_lo < n) ? rsqrtf((float)(__ldg(cnt + r_lo) + 1)) : 0.f;
    float di_hi = (r_hi < n) ? rsqrtf((float)(__ldg(cnt + r_hi) + 1)) : 0.f;

#pragma unroll
    for (int nt = 0; nt < 8; nt++) {
        int col = wc * 64 + nt * 8 + tg * 2;
        if (r_lo < n)
            *reinterpret_cast<__half2*>(h + (size_t)r_lo * FEAT + col) =
                __floats2half2_rn(acc[nt][0] * di_lo, acc[nt][1] * di_lo);
        if (r_hi < n)
            *reinterpret_cast<__half2*>(h + (size_t)r_hi * FEAT + col) =
                __floats2half2_rn(acc[nt][2] * di_hi, acc[nt][3] * di_hi);
    }
}

// ---------------------------------------------------------------------------
// Gather: warp per node. result = gelu(dd * (h'[node] + sum h'[s]) + b).
// GELU via hardware tanh.approx (MUFU.TANH) instead of normcdff's erfc
// software path (~100 instr -> ~7 instr).
// ---------------------------------------------------------------------------
__device__ __forceinline__ float gelu_fast(float v) {
    // 0.5*v*(1+tanh(0.7978845608*(v + 0.044715*v^3)))
    float t = fmaf(0.044715f * v, v * v, v) * 0.7978845608f;
    float th;
    asm("tanh.approx.f32 %0, %1;" : "=f"(th) : "f"(t));
    return 0.5f * v * (1.0f + th);
}

__device__ __forceinline__ void acc_row(float4& acc, const uint2* __restrict__ hb, int s) {
    uint2 hv = hb[s * 32];
    float2 fa = __half22float2(*reinterpret_cast<const __half2*>(&hv.x));
    float2 fb = __half22float2(*reinterpret_cast<const __half2*>(&hv.y));
    acc.x += fa.x; acc.y += fa.y; acc.z += fb.x; acc.w += fb.y;
}

__device__ __forceinline__ void acc_quad(float4& acc, const uint2 hv[4]) {
    const __half2* p0 = reinterpret_cast<const __half2*>(&hv[0]);
    const __half2* p1 = reinterpret_cast<const __half2*>(&hv[1]);
    const __half2* p2 = reinterpret_cast<const __half2*>(&hv[2]);
    const __half2* p3 = reinterpret_cast<const __half2*>(&hv[3]);
    __half2 xs = __hadd2(__hadd2(p0[0], p1[0]), __hadd2(p2[0], p3[0]));
    __half2 ys = __hadd2(__hadd2(p0[1], p1[1]), __hadd2(p2[1], p3[1]));
    float2 fx = __half22float2(xs);
    float2 fy = __half22float2(ys);
    acc.x += fx.x; acc.y += fx.y; acc.z += fy.x; acc.w += fy.y;
}

__global__ void __launch_bounds__(256)
gather_kernel(int* __restrict__ cnt, const int* __restrict__ list,
              const __half* __restrict__ h,
              const int* __restrict__ src, const int* __restrict__ dst,
              const int* __restrict__ ovf, const int* __restrict__ ovf_cnt,
              const float* __restrict__ b, float* out, int n) {
    int node = blockIdx.x * 8 + (threadIdx.x >> 5);
    if (node >= n) return;
    int lane = threadIdx.x & 31;

    int m = cnt[node];
    float dd = rsqrtf((float)(m + 1));

    const uint2* hb = reinterpret_cast<const uint2*>(h) + lane;  // row stride = 32 uint2

    float4 acc = make_float4(0.f, 0.f, 0.f, 0.f);
    acc_row(acc, hb, node);  // self loop: h'[node], exact fp32 path

    int mb = (m > CAP) ? CAP : m;
    const int* lp = list + (size_t)node * CAP;

    for (int base = 0; base < mb; base += 32) {
        int idx = base + lane;
        int s = (idx < mb) ? lp[idx] : 0;
        int cnum = mb - base; if (cnum > 32) cnum = 32;
        int j = 0;
        for (; j + 7 < cnum; j += 8) {
            uint2 hv[8];
#pragma unroll
            for (int q = 0; q < 8; q++) {
                int sq = __shfl_sync(0xFFFFFFFFu, s, j + q);
                hv[q] = hb[sq * 32];
            }
            acc_quad(acc, hv);
            acc_quad(acc, hv + 4);
        }
        for (; j < cnum; j++) {
            int sj = __shfl_sync(0xFFFFFFFFu, s, j);
            acc_row(acc, hb, sj);  // exact fp32 tail
        }
    }

    if (m > CAP) {  // inline overflow scan (ovf list empty in practice)
        int movf = *ovf_cnt;
        for (int i = 0; i < movf; i++) {
            int e = __ldg(ovf + i);
            if (__ldg(dst + e) == node) acc_row(acc, hb, __ldg(src + e));
        }
    }

    float4 bb = *(reinterpret_cast<const float4*>(b) + lane);
    acc.x = gelu_fast(fmaf(dd, acc.x, bb.x));
    acc.y = gelu_fast(fmaf(dd, acc.y, bb.y));
    acc.z = gelu_fast(fmaf(dd, acc.z, bb.z));
    acc.w = gelu_fast(fmaf(dd, acc.w, bb.w));
    *(reinterpret_cast<float4*>(out + (size_t)node * FEAT) + lane) = acc;

    // Reset cnt for the next replay (keeps kernel_launch deterministic across
    // graph replays; cnt is zero-initialized at module load).
    if (lane == 0) cnt[node] = 0;
}

// ---------------------------------------------------------------------------
// Launch: 4 kernels total (prep -> fill -> gemm -> gather)
// ---------------------------------------------------------------------------
extern "C" void kernel_launch(void* const* d_in, const int* in_sizes, int n_in,
                              void* d_out, int out_size) {
    const float* x  = (const float*)d_in[0];
    const int*   ei = (const int*)d_in[1];
    const float* W  = (const float*)d_in[2];
    const float* b  = (const float*)d_in[3];
    float* out = (float*)d_out;

    int n = in_sizes[0] / FEAT;
    int E = in_sizes[1] / 2;
    const int* src = ei;
    const int* dst = ei + E;

    __half *h_ptr, *wh_ptr;
    int *cnt_ptr, *list_ptr, *ovf_ptr, *ovfc_ptr;
    cudaGetSymbolAddress((void**)&h_ptr, g_h);
    cudaGetSymbolAddress((void**)&wh_ptr, g_wh);
    cudaGetSymbolAddress((void**)&cnt_ptr, g_cnt);
    cudaGetSymbolAddress((void**)&list_ptr, g_list);
    cudaGetSymbolAddress((void**)&ovf_ptr, g_ovf);
    cudaGetSymbolAddress((void**)&ovfc_ptr, g_ovf_cnt);

    prep_kernel<<<(FEAT * FEAT / 4 + 255) / 256, 256>>>(W, wh_ptr, ovfc_ptr);

    fill_kernel<<<(E + 255) / 256, 256>>>(src, dst, cnt_ptr, list_ptr, ovf_ptr, ovfc_ptr, E);

    int smem_bytes = (FEAT + BM) * WPADH * (int)sizeof(__half);  // ~68 KB
    cudaFuncSetAttribute(gemm_kernel, cudaFuncAttributeMaxDynamicSharedMemorySize, smem_bytes);
    gemm_kernel<<<(n + BM - 1) / BM, 512, smem_bytes>>>(x, wh_ptr, cnt_ptr, h_ptr, n);

    gather_kernel<<<(n + 7) / 8, 256>>>(cnt_ptr, list_ptr, h_ptr,
                                        src, dst, ovf_ptr, ovfc_ptr, b, out, n);
}